// round 7
// baseline (speedup 1.0000x reference)
#include <cuda_runtime.h>
#include <cuda_bf16.h>
#include <math.h>
#include <stdint.h>

// Problem constants
#define BB   128
#define QL   32
#define DL   1024
#define HH   768
#define DIMD 128
#define NEGV (-100000.0f)

// Scratch
__device__ float g_Qn[BB * QL * DIMD];
__device__ float g_qsq[BB * QL];
__device__ __nv_bfloat16 g_Wbf[DIMD * HH];   // bf16 copy of W

// ---------------------------------------------------------------------------
// Helpers (base-ISA sm_80+)
// ---------------------------------------------------------------------------
__device__ __forceinline__ unsigned smem_u32(const void* p) {
    return (unsigned)__cvta_generic_to_shared(p);
}
__device__ __forceinline__ void cp_async16(unsigned dst, const void* src) {
    asm volatile("cp.async.cg.shared.global [%0], [%1], 16;\n" :: "r"(dst), "l"(src));
}
__device__ __forceinline__ void cp_commit() {
    asm volatile("cp.async.commit_group;\n" ::: "memory");
}
__device__ __forceinline__ void cp_wait1() {
    asm volatile("cp.async.wait_group 1;\n" ::: "memory");
}
__device__ __forceinline__ void cp_wait0() {
    asm volatile("cp.async.wait_group 0;\n" ::: "memory");
}
__device__ __forceinline__ uint32_t f2bf2(float lo, float hi) {
    uint32_t r;
    asm("cvt.rn.bf16x2.f32 %0, %1, %2;" : "=r"(r) : "f"(hi), "f"(lo));
    return r;
}
__device__ __forceinline__ void ldsm_x4(uint32_t* r, uint32_t addr) {
    asm volatile("ldmatrix.sync.aligned.m8n8.x4.shared.b16 {%0,%1,%2,%3}, [%4];"
                 : "=r"(r[0]), "=r"(r[1]), "=r"(r[2]), "=r"(r[3]) : "r"(addr));
}
__device__ __forceinline__ void sts128(uint32_t addr, uint32_t r0, uint32_t r1,
                                       uint32_t r2, uint32_t r3) {
    asm volatile("st.shared.v4.b32 [%0], {%1,%2,%3,%4};"
                 :: "r"(addr), "r"(r0), "r"(r1), "r"(r2), "r"(r3) : "memory");
}
__device__ __forceinline__ void sts32(uint32_t addr, uint32_t r0) {
    asm volatile("st.shared.b32 [%0], %1;" :: "r"(addr), "r"(r0) : "memory");
}
__device__ __forceinline__ void mma_bf16(float* c, const uint32_t* a, const uint32_t* b) {
    asm volatile(
        "mma.sync.aligned.m16n8k16.row.col.f32.bf16.bf16.f32 "
        "{%0,%1,%2,%3}, {%4,%5,%6,%7}, {%8,%9}, {%0,%1,%2,%3};"
        : "+f"(c[0]), "+f"(c[1]), "+f"(c[2]), "+f"(c[3])
        : "r"(a[0]), "r"(a[1]), "r"(a[2]), "r"(a[3]), "r"(b[0]), "r"(b[1]));
}

// ---------------------------------------------------------------------------
// Kernel 1: W conversion + Q projection + L2 normalize. 128 CTAs, 512 thr.
// ---------------------------------------------------------------------------
__global__ __launch_bounds__(512, 1)
void q_proj_kernel(const float* __restrict__ Qe, const float* __restrict__ W)
{
    __shared__ float As[32 * 33];
    __shared__ float Ws[32 * 132];

    const int b   = blockIdx.x;
    const int tid = threadIdx.x;
    const int tx  = tid & 15;       // 8 output cols
    const int ty  = tid >> 4;       // 1 output row (0..31)
    const float* A = Qe + (size_t)b * QL * HH;

    // Fold-in: W fp32 -> bf16 (this CTA's slice: 192 float4s)
    if (tid < 192) {
        int i = b * 192 + tid;
        float4 v = *(const float4*)(W + (size_t)i * 4);
        *(uint2*)((char*)g_Wbf + (size_t)i * 8) =
            make_uint2(f2bf2(v.x, v.y), f2bf2(v.z, v.w));
    }

    float acc[8];
#pragma unroll
    for (int j = 0; j < 8; j++) acc[j] = 0.0f;

    for (int kk = 0; kk < HH; kk += 32) {
        __syncthreads();
        if (tid < 256) {
            int r  = tid >> 3;
            int c4 = tid & 7;
            float4 v = *(const float4*)(A + (size_t)r * HH + kk + c4 * 4);
            As[(c4 * 4 + 0) * 33 + r] = v.x;
            As[(c4 * 4 + 1) * 33 + r] = v.y;
            As[(c4 * 4 + 2) * 33 + r] = v.z;
            As[(c4 * 4 + 3) * 33 + r] = v.w;
        }
#pragma unroll
        for (int l = 0; l < 2; l++) {
            int lin = tid + l * 512;
            int r   = lin >> 3;
            int c4  = lin & 7;
            float4 v = *(const float4*)(W + (size_t)r * HH + kk + c4 * 4);
            Ws[(c4 * 4 + 0) * 132 + r] = v.x;
            Ws[(c4 * 4 + 1) * 132 + r] = v.y;
            Ws[(c4 * 4 + 2) * 132 + r] = v.z;
            Ws[(c4 * 4 + 3) * 132 + r] = v.w;
        }
        __syncthreads();

#pragma unroll 8
        for (int k = 0; k < 32; k++) {
            float a0 = As[k * 33 + ty];
            float4 w0 = *(const float4*)&Ws[k * 132 + tx * 8];
            float4 w1 = *(const float4*)&Ws[k * 132 + tx * 8 + 4];
            acc[0] = fmaf(a0, w0.x, acc[0]);
            acc[1] = fmaf(a0, w0.y, acc[1]);
            acc[2] = fmaf(a0, w0.z, acc[2]);
            acc[3] = fmaf(a0, w0.w, acc[3]);
            acc[4] = fmaf(a0, w1.x, acc[4]);
            acc[5] = fmaf(a0, w1.y, acc[5]);
            acc[6] = fmaf(a0, w1.z, acc[6]);
            acc[7] = fmaf(a0, w1.w, acc[7]);
        }
    }

    {
        float s = 0.0f;
#pragma unroll
        for (int j = 0; j < 8; j++) s += acc[j] * acc[j];
#pragma unroll
        for (int o = 8; o >= 1; o >>= 1) s += __shfl_xor_sync(0xffffffffu, s, o, 16);
        float inv = 1.0f / fmaxf(sqrtf(s), 1e-12f);
#pragma unroll
        for (int j = 0; j < 8; j++) acc[j] *= inv;
        *(float4*)(g_Qn + ((size_t)b * QL + ty) * DIMD + tx * 8) =
            make_float4(acc[0], acc[1], acc[2], acc[3]);
        *(float4*)(g_Qn + ((size_t)b * QL + ty) * DIMD + tx * 8 + 4) =
            make_float4(acc[4], acc[5], acc[6], acc[7]);
        if (tx == 0) g_qsq[b * QL + ty] = s * inv * inv;
    }
}

// ---------------------------------------------------------------------------
// Kernel 2: fused D projection (bf16 mma, KC=128) + mask + normalize + MMA
// scoring. 128 CTAs (one batch), 512 threads.
//
// SMEM bytes:
//   Qbf   0       8704    (32 x 128 bf16, stride 272)
//   Dbf   8704    34816   (128 x 128 bf16, stride 272)
//   A0    43520   34816   (128 x 128 bf16, stride 272)
//   A1    78336   34816
//   W0    113152  34816
//   W1    147968  34816
//   W2    182784  34816
//   rs    217600  2048
//   dsq   219648  512
//   qsq   220160  128
//   qpart 220288  1024
//   total 221312
// ---------------------------------------------------------------------------
#define SM_QBF   0
#define SM_DBF   8704
#define SM_A0    43520
#define SM_A1    78336
#define SM_W0    113152
#define SM_W1    147968
#define SM_W2    182784
#define SM_RS    217600
#define SM_DSQ   219648
#define SM_QSQ   220160
#define SM_QPART 220288
#define SM_TOTAL 221312

#define RSTR    272          // bf16 tile row stride (128 bf16 + 8 pad)
#define KC      128
#define NCHUNK  (HH / KC)    // 6

__global__ __launch_bounds__(512, 1)
void score_kernel(const float* __restrict__ Demb,
                  const int*   __restrict__ ids,
                  const int*   __restrict__ attn,
                  float*       __restrict__ out)
{
    extern __shared__ char smc[];
    float* rs    = (float*)(smc + SM_RS);
    float* dsq   = (float*)(smc + SM_DSQ);
    float* qsq   = (float*)(smc + SM_QSQ);
    float* qpart = (float*)(smc + SM_QPART);

    const uint32_t base = smem_u32(smc);

    const int b    = blockIdx.x;
    const int tid  = threadIdx.x;
    const int lane = tid & 31;
    const int warp = tid >> 5;
    const int warpM = warp >> 2;       // 0..3 -> rows warpM*32..+31
    const int warpN = warp & 3;        // 0..3 -> cols warpN*32..+31
    const int g    = lane >> 2;        // 0..7
    const int t    = lane & 3;         // 0..3

    // Staging coords: one A row per thread, 32 float cols (4 pair-blocks)
    const int ar  = tid >> 2;          // 0..127
    const int seg = tid & 3;           // 0..3

    // Main-GEMM ldmatrix offsets
    const uint32_t aoff = (uint32_t)(warpM * 32 + (lane & 15)) * RSTR
                        + ((lane >> 4) & 1) * 16;
    const uint32_t boff = (uint32_t)(warpN * 32 + ((lane >> 4) & 1) * 8 + (lane & 7)) * RSTR
                        + ((lane >> 3) & 1) * 16;
    const uint32_t Au[2] = {base + SM_A0 + aoff, base + SM_A1 + aoff};
    const uint32_t Wu[3] = {base + SM_W0 + boff, base + SM_W1 + boff, base + SM_W2 + boff};
    const uint32_t Wdst[3] = {base + SM_W0, base + SM_W1, base + SM_W2};
    const uint32_t Adst[2] = {base + SM_A0, base + SM_A1};

    // Score-GEMM offsets: each warp does m16 x two n8 tiles (n0 and n0+64)
    const int mq = (warp & 1) * 16;
    const int n0 = (warp >> 1) * 8;
    const uint32_t qa = base + SM_QBF + (uint32_t)(mq + (lane & 15)) * RSTR
                      + ((lane >> 4) & 1) * 16;
    const uint32_t da0 = base + SM_DBF + (uint32_t)(n0 + (lane & 7)) * RSTR
                       + ((lane >> 3) & 3) * 16;
    const uint32_t da1 = da0 + 64 * RSTR;

    // Stage Qbf (fp32 g_Qn -> bf16 smem) + qsq
    if (tid < 256) {
        int row = tid >> 3, sg = tid & 7;     // 16 floats per sg
        const float* p = g_Qn + ((size_t)b * QL + row) * DIMD + sg * 16;
        float4 v0 = *(const float4*)(p);
        float4 v1 = *(const float4*)(p + 4);
        float4 v2 = *(const float4*)(p + 8);
        float4 v3 = *(const float4*)(p + 12);
        uint32_t addr = base + SM_QBF + row * RSTR + sg * 32;
        sts128(addr,      f2bf2(v0.x, v0.y), f2bf2(v0.z, v0.w),
                          f2bf2(v1.x, v1.y), f2bf2(v1.z, v1.w));
        sts128(addr + 16, f2bf2(v2.x, v2.y), f2bf2(v2.z, v2.w),
                          f2bf2(v3.x, v3.y), f2bf2(v3.z, v3.w));
    }
    if (tid < 32) qsq[tid] = g_qsq[b * QL + tid];

    float lm0 = NEGV, lm1 = NEGV;      // running max for query rows mq+g, mq+g+8

    for (int t0 = 0; t0 < DL; t0 += 128) {
        const float* Ag = Demb + ((size_t)b * DL + t0) * HH;
        const float* arow = Ag + (size_t)ar * HH;

        float acc[2][4][4];
#pragma unroll
        for (int m = 0; m < 2; m++)
#pragma unroll
            for (int n = 0; n < 4; n++)
#pragma unroll
                for (int r = 0; r < 4; r++) acc[m][n][r] = 0.0f;

        // Prologue: LDG A chunk0 -> regs; cp.async W chunk0
        float4 ra[8];
#pragma unroll
        for (int p = 0; p < 4; p++) {
            const float* q = arow + (seg + 4 * p) * 8;
            ra[2 * p]     = *(const float4*)(q);
            ra[2 * p + 1] = *(const float4*)(q + 4);
        }
#pragma unroll
        for (int l = 0; l < 4; l++) {
            int lin = tid + l * 512;
            int wr  = lin >> 4;
            int c16 = lin & 15;
            cp_async16(Wdst[0] + wr * RSTR + c16 * 16,
                       (const char*)g_Wbf + (size_t)wr * (HH * 2) + c16 * 16);
        }
        cp_commit();

        for (int s = 0; s < NCHUNK; s++) {
            // STS chunk s A (regs -> bf16 smem)
            const uint32_t abuf = Adst[s & 1] + (uint32_t)ar * RSTR;
#pragma unroll
            for (int p = 0; p < 4; p++) {
                sts128(abuf + (seg + 4 * p) * 16,
                       f2bf2(ra[2*p].x, ra[2*p].y),   f2bf2(ra[2*p].z, ra[2*p].w),
                       f2bf2(ra[2*p+1].x, ra[2*p+1].y), f2bf2(ra[2*p+1].z, ra[2*p+1].w));
            }

            if (s < NCHUNK - 1) {
#pragma unroll
                for (int p = 0; p < 4; p++) {
                    const float* q = arow + (s + 1) * KC + (seg + 4 * p) * 8;
                    ra[2 * p]     = *(const float4*)(q);
                    ra[2 * p + 1] = *(const float4*)(q + 4);
                }
                uint32_t wdst = Wdst[(s + 1) % 3];
#pragma unroll
                for (int l = 0; l < 4; l++) {
                    int lin = tid + l * 512;
                    int wr  = lin >> 4;
                    int c16 = lin & 15;
                    cp_async16(wdst + wr * RSTR + c16 * 16,
                               (const char*)g_Wbf + (size_t)wr * (HH * 2)
                                   + (s + 1) * (KC * 2) + c16 * 16);
                }
                cp_commit();
                cp_wait1();
            } else {
                cp_wait0();
            }
            __syncthreads();

            const uint32_t au = Au[s & 1];
            const uint32_t wb = Wu[s % 3];
#pragma unroll
            for (int kb = 0; kb < 8; kb++) {
                uint32_t a0[4], a1[4], b0[4], b1[4];
                ldsm_x4(a0, au + kb * 32);
                ldsm_x4(a1, au + 16 * RSTR + kb * 32);
                ldsm_x4(b0, wb + kb * 32);
                ldsm_x4(b1, wb + 16 * RSTR + kb * 32);
                mma_bf16(acc[0][0], a0, b0);
                mma_bf16(acc[0][1], a0, b0 + 2);
                mma_bf16(acc[0][2], a0, b1);
                mma_bf16(acc[0][3], a0, b1 + 2);
                mma_bf16(acc[1][0], a1, b0);
                mma_bf16(acc[1][1], a1, b0 + 2);
                mma_bf16(acc[1][2], a1, b1);
                mma_bf16(acc[1][3], a1, b1 + 2);
            }
        }

        // ---- Epilogue: mask, row-norm partials ----
#pragma unroll
        for (int m = 0; m < 2; m++) {
#pragma unroll
            for (int h = 0; h < 2; h++) {
                int row = warpM * 32 + m * 16 + h * 8 + g;
                bool z  = (ids[b * DL + t0 + row] == 0);
                float s = 0.0f;
#pragma unroll
                for (int n = 0; n < 4; n++) {
                    if (z) { acc[m][n][h * 2] = 0.0f; acc[m][n][h * 2 + 1] = 0.0f; }
                    float x = acc[m][n][h * 2];
                    float y = acc[m][n][h * 2 + 1];
                    s += x * x + y * y;
                }
                s += __shfl_xor_sync(0xffffffffu, s, 1, 4);
                s += __shfl_xor_sync(0xffffffffu, s, 2, 4);
                if (t == 0) rs[warpN * 128 + row] = s;
            }
        }
        __syncthreads();

        // ---- Normalize -> bf16 Dbf + dsq ----
#pragma unroll
        for (int m = 0; m < 2; m++) {
#pragma unroll
            for (int h = 0; h < 2; h++) {
                int row   = warpM * 32 + m * 16 + h * 8 + g;
                float st  = rs[row] + rs[128 + row] + rs[256 + row] + rs[384 + row];
                float inv = 1.0f / fmaxf(sqrtf(st), 1e-12f);
#pragma unroll
                for (int n = 0; n < 4; n++) {
                    int col = warpN * 32 + n * 8 + t * 2;
                    uint32_t pk = f2bf2(acc[m][n][h * 2] * inv, acc[m][n][h * 2 + 1] * inv);
                    sts32(base + SM_DBF + (uint32_t)row * RSTR + col * 2, pk);
                }
                if (warpN == 0 && t == 0) dsq[row] = st * inv * inv;
            }
        }
        __syncthreads();

        // ---- Score GEMM: S = Q . D^T, two n8 tiles per warp (n0, n0+64) ----
        {
            const float q0 = qsq[mq + g], q1 = qsq[mq + g + 8];
#pragma unroll
            for (int half = 0; half < 2; half++) {
                const uint32_t da = half ? da1 : da0;
                float sacc[4] = {0.0f, 0.0f, 0.0f, 0.0f};
#pragma unroll
                for (int kb = 0; kb < 8; kb += 2) {
                    uint32_t aA[4], aB[4], bb[4];
                    ldsm_x4(aA, qa + kb * 32);
                    ldsm_x4(aB, qa + (kb + 1) * 32);
                    ldsm_x4(bb, da + kb * 32);
                    mma_bf16(sacc, aA, bb);
                    mma_bf16(sacc, aB, bb + 2);
                }
                const int col0 = n0 + half * 64 + t * 2;
                const int col1 = col0 + 1;
                const bool k0  = attn[b * DL + t0 + col0] != 0;
                const bool k1  = attn[b * DL + t0 + col1] != 0;
                const float d0 = dsq[col0], d1 = dsq[col1];
                float s00 = k0 ? (2.0f * sacc[0] - q0 - d0) : NEGV;
                float s01 = k1 ? (2.0f * sacc[1] - q0 - d1) : NEGV;
                float s10 = k0 ? (2.0f * sacc[2] - q1 - d0) : NEGV;
                float s11 = k1 ? (2.0f * sacc[3] - q1 - d1) : NEGV;
                lm0 = fmaxf(lm0, fmaxf(s00, s01));
                lm1 = fmaxf(lm1, fmaxf(s10, s11));
            }
        }
        __syncthreads();   // Dbf/rs reuse next tile
    }

    // Reduce lm over t (4 lanes), write per-warp partials
    lm0 = fmaxf(lm0, __shfl_xor_sync(0xffffffffu, lm0, 1));
    lm0 = fmaxf(lm0, __shfl_xor_sync(0xffffffffu, lm0, 2));
    lm1 = fmaxf(lm1, __shfl_xor_sync(0xffffffffu, lm1, 1));
    lm1 = fmaxf(lm1, __shfl_xor_sync(0xffffffffu, lm1, 2));
    if (t == 0) {
        int wc = warp >> 1;
        qpart[(mq + g) * 8 + wc]     = lm0;
        qpart[(mq + g + 8) * 8 + wc] = lm1;
    }
    __syncthreads();

    if (tid < 32) {
        float v = NEGV;
#pragma unroll
        for (int j = 0; j < 8; j++) v = fmaxf(v, qpart[tid * 8 + j]);
#pragma unroll
        for (int o = 16; o >= 1; o >>= 1) v += __shfl_xor_sync(0xffffffffu, v, o, 32);
        if (tid == 0) out[b] = v;
    }
}

// ---------------------------------------------------------------------------
extern "C" void kernel_launch(void* const* d_in, const int* in_sizes, int n_in,
                              void* d_out, int out_size)
{
    const float* Qe   = (const float*)d_in[0];  // [128,32,768]
    const float* De   = (const float*)d_in[1];  // [128,1024,768]
    const int*   ids  = (const int*)  d_in[2];  // [128,1024]
    const int*   attn = (const int*)  d_in[3];  // [128,1024]
    const float* W    = (const float*)d_in[4];  // [128,768]
    float*       out  = (float*)d_out;          // [128]

    q_proj_kernel<<<BB, 512>>>(Qe, W);

    cudaFuncSetAttribute(score_kernel, cudaFuncAttributeMaxDynamicSharedMemorySize,
                         SM_TOTAL);
    score_kernel<<<BB, 512, SM_TOTAL>>>(De, ids, attn, out);
}

// round 9
// speedup vs baseline: 1.1024x; 1.1024x over previous
#include <cuda_runtime.h>
#include <cuda_bf16.h>
#include <math.h>
#include <stdint.h>

// Problem constants
#define BB   128
#define QL   32
#define DL   1024
#define HH   768
#define DIMD 128
#define NEGV (-100000.0f)

// Scratch
__device__ float g_Qn[BB * QL * DIMD];
__device__ float g_qsq[BB * QL];
__device__ __nv_bfloat16 g_Wbf[DIMD * HH];   // bf16 copy of W
__device__ float g_part[2 * BB * QL];        // per-(CTA,query) max partials

// ---------------------------------------------------------------------------
// Helpers (base-ISA sm_80+)
// ---------------------------------------------------------------------------
__device__ __forceinline__ unsigned smem_u32(const void* p) {
    return (unsigned)__cvta_generic_to_shared(p);
}
__device__ __forceinline__ void cp_async16(unsigned dst, const void* src) {
    asm volatile("cp.async.cg.shared.global [%0], [%1], 16;\n" :: "r"(dst), "l"(src));
}
__device__ __forceinline__ void cp_commit() {
    asm volatile("cp.async.commit_group;\n" ::: "memory");
}
__device__ __forceinline__ void cp_wait1() {
    asm volatile("cp.async.wait_group 1;\n" ::: "memory");
}
__device__ __forceinline__ void cp_wait0() {
    asm volatile("cp.async.wait_group 0;\n" ::: "memory");
}
__device__ __forceinline__ uint32_t f2bf2(float lo, float hi) {
    uint32_t r;
    asm("cvt.rn.bf16x2.f32 %0, %1, %2;" : "=r"(r) : "f"(hi), "f"(lo));
    return r;
}
__device__ __forceinline__ void ldsm_x4(uint32_t* r, uint32_t addr) {
    asm volatile("ldmatrix.sync.aligned.m8n8.x4.shared.b16 {%0,%1,%2,%3}, [%4];"
                 : "=r"(r[0]), "=r"(r[1]), "=r"(r[2]), "=r"(r[3]) : "r"(addr));
}
__device__ __forceinline__ void sts128(uint32_t addr, uint32_t r0, uint32_t r1,
                                       uint32_t r2, uint32_t r3) {
    asm volatile("st.shared.v4.b32 [%0], {%1,%2,%3,%4};"
                 :: "r"(addr), "r"(r0), "r"(r1), "r"(r2), "r"(r3) : "memory");
}
__device__ __forceinline__ void sts32(uint32_t addr, uint32_t r0) {
    asm volatile("st.shared.b32 [%0], %1;" :: "r"(addr), "r"(r0) : "memory");
}
__device__ __forceinline__ void mma_bf16(float* c, const uint32_t* a, const uint32_t* b) {
    asm volatile(
        "mma.sync.aligned.m16n8k16.row.col.f32.bf16.bf16.f32 "
        "{%0,%1,%2,%3}, {%4,%5,%6,%7}, {%8,%9}, {%0,%1,%2,%3};"
        : "+f"(c[0]), "+f"(c[1]), "+f"(c[2]), "+f"(c[3])
        : "r"(a[0]), "r"(a[1]), "r"(a[2]), "r"(a[3]), "r"(b[0]), "r"(b[1]));
}

// ---------------------------------------------------------------------------
// Kernel 0: W fp32 -> bf16
// ---------------------------------------------------------------------------
__global__ void wconv_kernel(const float* __restrict__ W)
{
    int i = blockIdx.x * 256 + threadIdx.x;
    float4 v = *(const float4*)(W + (size_t)i * 4);
    *(uint2*)((char*)g_Wbf + (size_t)i * 8) = make_uint2(f2bf2(v.x, v.y), f2bf2(v.z, v.w));
}

// ---------------------------------------------------------------------------
// Kernel 1: Q projection + L2 normalize (fp32). 128 CTAs, 256 thr.
// ---------------------------------------------------------------------------
__global__ __launch_bounds__(256, 1)
void q_proj_kernel(const float* __restrict__ Qe, const float* __restrict__ W)
{
    __shared__ float As[32 * 33];
    __shared__ float Ws[32 * 132];

    const int b   = blockIdx.x;
    const int tid = threadIdx.x;
    const int tx  = tid & 15;
    const int ty  = tid >> 4;
    const float* A = Qe + (size_t)b * QL * HH;

    float acc[2][8];
#pragma unroll
    for (int i = 0; i < 2; i++)
#pragma unroll
        for (int j = 0; j < 8; j++) acc[i][j] = 0.0f;

    for (int kk = 0; kk < HH; kk += 32) {
        __syncthreads();
        {
            int r  = tid >> 3;
            int c4 = tid & 7;
            float4 v = *(const float4*)(A + (size_t)r * HH + kk + c4 * 4);
            As[(c4 * 4 + 0) * 33 + r] = v.x;
            As[(c4 * 4 + 1) * 33 + r] = v.y;
            As[(c4 * 4 + 2) * 33 + r] = v.z;
            As[(c4 * 4 + 3) * 33 + r] = v.w;
        }
#pragma unroll
        for (int l = 0; l < 4; l++) {
            int lin = tid + l * 256;
            int r   = lin >> 3;
            int c4  = lin & 7;
            float4 v = *(const float4*)(W + (size_t)r * HH + kk + c4 * 4);
            Ws[(c4 * 4 + 0) * 132 + r] = v.x;
            Ws[(c4 * 4 + 1) * 132 + r] = v.y;
            Ws[(c4 * 4 + 2) * 132 + r] = v.z;
            Ws[(c4 * 4 + 3) * 132 + r] = v.w;
        }
        __syncthreads();

#pragma unroll 8
        for (int k = 0; k < 32; k++) {
            float a0 = As[k * 33 + ty * 2];
            float a1 = As[k * 33 + ty * 2 + 1];
            float4 w0 = *(const float4*)&Ws[k * 132 + tx * 8];
            float4 w1 = *(const float4*)&Ws[k * 132 + tx * 8 + 4];
            float w[8] = {w0.x, w0.y, w0.z, w0.w, w1.x, w1.y, w1.z, w1.w};
#pragma unroll
            for (int j = 0; j < 8; j++) {
                acc[0][j] = fmaf(a0, w[j], acc[0][j]);
                acc[1][j] = fmaf(a1, w[j], acc[1][j]);
            }
        }
    }

#pragma unroll
    for (int i = 0; i < 2; i++) {
        float s = 0.0f;
#pragma unroll
        for (int j = 0; j < 8; j++) s += acc[i][j] * acc[i][j];
#pragma unroll
        for (int o = 8; o >= 1; o >>= 1) s += __shfl_xor_sync(0xffffffffu, s, o, 16);
        float inv = 1.0f / fmaxf(sqrtf(s), 1e-12f);
        int   m   = ty * 2 + i;
#pragma unroll
        for (int j = 0; j < 8; j++) acc[i][j] *= inv;
        *(float4*)(g_Qn + ((size_t)b * QL + m) * DIMD + tx * 8) =
            make_float4(acc[i][0], acc[i][1], acc[i][2], acc[i][3]);
        *(float4*)(g_Qn + ((size_t)b * QL + m) * DIMD + tx * 8 + 4) =
            make_float4(acc[i][4], acc[i][5], acc[i][6], acc[i][7]);
        if (tx == 0) g_qsq[b * QL + m] = s * inv * inv;
    }
}

// ---------------------------------------------------------------------------
// Kernel 2: fused D projection + mask + normalize + MMA scoring.
// Grid 256 (2 CTAs per batch, half the docs each), 256 threads, 2 CTAs/SM.
// CTA doc-tile 64 x 128, warp tile 16x64 (8 warps), KC=64.
//
// SMEM bytes:
//   Qbf   0       8704    (32 x 128 bf16, stride 272)
//   Dbf   8704    17408   (64 x 128 bf16, stride 272)
//   A0    26112   9216    (64 x 64 bf16, stride 144)
//   A1    35328   9216
//   W0    44544   18432   (128 x 64 bf16, stride 144)
//   W1    62976   18432
//   W2    81408   18432
//   rs    99840   512     (2 x 64 f32)
//   dsq   100352  256
//   qsq   100608  128
//   qpart 100736  512     (32 x 4 f32)
//   total 101248
// ---------------------------------------------------------------------------
#define SM_QBF   0
#define SM_DBF   8704
#define SM_A0    26112
#define SM_A1    35328
#define SM_W0    44544
#define SM_W1    62976
#define SM_W2    81408
#define SM_RS    99840
#define SM_DSQ   100352
#define SM_QSQ   100608
#define SM_QPART 100736
#define SM_TOTAL 101248

#define RSTR    144          // A/W row stride (64 bf16 + pad)
#define QSTR    272          // Qbf/Dbf row stride (128 bf16 + pad)
#define KC      64
#define NCHUNK  (HH / KC)    // 12
#define DTILE   64
#define NTILE   8            // tiles per CTA (512 docs)

__global__ __launch_bounds__(256, 2)
void score_kernel(const float* __restrict__ Demb,
                  const int*   __restrict__ ids,
                  const int*   __restrict__ attn)
{
    extern __shared__ char smc[];
    float* rs    = (float*)(smc + SM_RS);
    float* dsq   = (float*)(smc + SM_DSQ);
    float* qsq   = (float*)(smc + SM_QSQ);
    float* qpart = (float*)(smc + SM_QPART);

    const uint32_t base = smem_u32(smc);

    const int bid  = blockIdx.x;
    const int b    = bid >> 1;
    const int dbase = (bid & 1) * (NTILE * DTILE);
    const int tid  = threadIdx.x;
    const int lane = tid & 31;
    const int warp = tid >> 5;
    const int warpM = warp >> 1;       // 0..3 -> rows warpM*16..+15
    const int warpN = warp & 1;        // 0..1 -> cols warpN*64..+63
    const int g    = lane >> 2;        // 0..7
    const int t    = lane & 3;         // 0..3

    // A staging: ar row (0..63), seg quarter-row (16 floats)
    const int ar  = tid >> 2;
    const int seg = tid & 3;

    // Main-GEMM ldmatrix offsets
    const uint32_t aoff = (uint32_t)(warpM * 16 + (lane & 15)) * RSTR
                        + ((lane >> 4) & 1) * 16;
    const uint32_t boff = (uint32_t)(warpN * 64 + ((lane >> 4) & 1) * 8 + (lane & 7)) * RSTR
                        + ((lane >> 3) & 1) * 16;
    const uint32_t Au[2]   = {base + SM_A0 + aoff, base + SM_A1 + aoff};
    const uint32_t Adst[2] = {base + SM_A0, base + SM_A1};
    const uint32_t Wu[3]   = {base + SM_W0 + boff, base + SM_W1 + boff, base + SM_W2 + boff};
    const uint32_t Wdst[3] = {base + SM_W0, base + SM_W1, base + SM_W2};

    // Score-GEMM offsets: warp does m16 (mq) x two n8 tiles (n0, n0+32)
    const int mq = (warp & 1) * 16;
    const int n0 = (warp >> 1) * 8;    // 0,8,16,24
    const uint32_t qa = base + SM_QBF + (uint32_t)(mq + (lane & 15)) * QSTR
                      + ((lane >> 4) & 1) * 16;
    const uint32_t da0 = base + SM_DBF + (uint32_t)(n0 + (lane & 7)) * QSTR
                       + ((lane >> 3) & 3) * 16;
    const uint32_t da1 = da0 + 32 * QSTR;

    // Stage Qbf (fp32 g_Qn -> bf16 smem) + qsq
    {
        int row = tid >> 3, sg = tid & 7;     // 16 floats per sg
        const float* p = g_Qn + ((size_t)b * QL + row) * DIMD + sg * 16;
        float4 v0 = *(const float4*)(p);
        float4 v1 = *(const float4*)(p + 4);
        float4 v2 = *(const float4*)(p + 8);
        float4 v3 = *(const float4*)(p + 12);
        uint32_t addr = base + SM_QBF + row * QSTR + sg * 32;
        sts128(addr,      f2bf2(v0.x, v0.y), f2bf2(v0.z, v0.w),
                          f2bf2(v1.x, v1.y), f2bf2(v1.z, v1.w));
        sts128(addr + 16, f2bf2(v2.x, v2.y), f2bf2(v2.z, v2.w),
                          f2bf2(v3.x, v3.y), f2bf2(v3.z, v3.w));
    }
    if (tid < 32) qsq[tid] = g_qsq[b * QL + tid];

    float lm0 = NEGV, lm1 = NEGV;      // running max for query rows mq+g, mq+g+8

    for (int ti = 0; ti < NTILE; ti++) {
        const int t0 = dbase + ti * DTILE;
        const float* arow = Demb + ((size_t)b * DL + t0 + ar) * HH;

        float acc[8][4];
#pragma unroll
        for (int n = 0; n < 8; n++)
#pragma unroll
            for (int r = 0; r < 4; r++) acc[n][r] = 0.0f;

        // Prologue: LDG A chunk0 -> regs; cp.async W chunk0 -> W0
        float4 ra[4];
#pragma unroll
        for (int p = 0; p < 4; p++)
            ra[p] = *(const float4*)(arow + seg * 16 + p * 4);
#pragma unroll
        for (int l = 0; l < 4; l++) {
            int lin = tid + l * 256;   // 0..1023
            int wr  = lin >> 3;        // 0..127
            int c16 = lin & 7;         // 0..7 (8 x 16B = 128B = 64 bf16)
            cp_async16(Wdst[0] + wr * RSTR + c16 * 16,
                       (const char*)g_Wbf + (size_t)wr * (HH * 2) + c16 * 16);
        }
        cp_commit();

        for (int s = 0; s < NCHUNK; s++) {
            // STS chunk s A (regs -> bf16 smem)
            const uint32_t abuf = Adst[s & 1] + (uint32_t)ar * RSTR + seg * 32;
            sts128(abuf,      f2bf2(ra[0].x, ra[0].y), f2bf2(ra[0].z, ra[0].w),
                              f2bf2(ra[1].x, ra[1].y), f2bf2(ra[1].z, ra[1].w));
            sts128(abuf + 16, f2bf2(ra[2].x, ra[2].y), f2bf2(ra[2].z, ra[2].w),
                              f2bf2(ra[3].x, ra[3].y), f2bf2(ra[3].z, ra[3].w));

            if (s < NCHUNK - 1) {
#pragma unroll
                for (int p = 0; p < 4; p++)
                    ra[p] = *(const float4*)(arow + (s + 1) * KC + seg * 16 + p * 4);
                uint32_t wdst = Wdst[(s + 1) % 3];
#pragma unroll
                for (int l = 0; l < 4; l++) {
                    int lin = tid + l * 256;
                    int wr  = lin >> 3;
                    int c16 = lin & 7;
                    cp_async16(wdst + wr * RSTR + c16 * 16,
                               (const char*)g_Wbf + (size_t)wr * (HH * 2)
                                   + (s + 1) * (KC * 2) + c16 * 16);
                }
                cp_commit();
                cp_wait1();
            } else {
                cp_wait0();
            }
            __syncthreads();

            const uint32_t au = Au[s & 1];
            const uint32_t wb = Wu[s % 3];
#pragma unroll
            for (int kb = 0; kb < 4; kb++) {
                uint32_t a[4];
                ldsm_x4(a, au + kb * 32);
#pragma unroll
                for (int j = 0; j < 4; j++) {
                    uint32_t bfr[4];
                    ldsm_x4(bfr, wb + j * 16 * RSTR + kb * 32);
                    mma_bf16(acc[2 * j],     a, bfr);
                    mma_bf16(acc[2 * j + 1], a, bfr + 2);
                }
            }
            __syncthreads();   // A[s&1] reusable at s+2; W rotation safe (3 bufs)
        }

        // ---- Epilogue: mask + row-norm partials ----
#pragma unroll
        for (int h = 0; h < 2; h++) {
            int row = warpM * 16 + h * 8 + g;
            bool z  = (ids[b * DL + t0 + row] == 0);
            float s = 0.0f;
#pragma unroll
            for (int n = 0; n < 8; n++) {
                if (z) { acc[n][h * 2] = 0.0f; acc[n][h * 2 + 1] = 0.0f; }
                float x = acc[n][h * 2];
                float y = acc[n][h * 2 + 1];
                s += x * x + y * y;
            }
            s += __shfl_xor_sync(0xffffffffu, s, 1, 4);
            s += __shfl_xor_sync(0xffffffffu, s, 2, 4);
            if (t == 0) rs[warpN * 64 + row] = s;
        }
        __syncthreads();

        // ---- Normalize -> bf16 Dbf + dsq ----
#pragma unroll
        for (int h = 0; h < 2; h++) {
            int row   = warpM * 16 + h * 8 + g;
            float st  = rs[row] + rs[64 + row];
            float inv = 1.0f / fmaxf(sqrtf(st), 1e-12f);
#pragma unroll
            for (int n = 0; n < 8; n++) {
                int col = warpN * 64 + n * 8 + t * 2;
                uint32_t pk = f2bf2(acc[n][h * 2] * inv, acc[n][h * 2 + 1] * inv);
                sts32(base + SM_DBF + (uint32_t)row * QSTR + col * 2, pk);
            }
            if (warpN == 0 && t == 0) dsq[row] = st * inv * inv;
        }
        __syncthreads();

        // ---- Score GEMM: S = Q . D^T, two n8 tiles per warp (n0, n0+32) ----
        {
            const float q0 = qsq[mq + g], q1 = qsq[mq + g + 8];
#pragma unroll
            for (int half = 0; half < 2; half++) {
                const uint32_t da = half ? da1 : da0;
                float sacc[4] = {0.0f, 0.0f, 0.0f, 0.0f};
#pragma unroll
                for (int kb = 0; kb < 8; kb += 2) {
                    uint32_t aA[4], aB[4], bb[4];
                    ldsm_x4(aA, qa + kb * 32);
                    ldsm_x4(aB, qa + (kb + 1) * 32);
                    ldsm_x4(bb, da + kb * 32);
                    mma_bf16(sacc, aA, bb);
                    mma_bf16(sacc, aB, bb + 2);
                }
                const int col0 = n0 + half * 32 + t * 2;
                const int col1 = col0 + 1;
                const bool k0  = attn[b * DL + t0 + col0] != 0;
                const bool k1  = attn[b * DL + t0 + col1] != 0;
                const float d0 = dsq[col0], d1 = dsq[col1];
                float s00 = k0 ? (2.0f * sacc[0] - q0 - d0) : NEGV;
                float s01 = k1 ? (2.0f * sacc[1] - q0 - d1) : NEGV;
                float s10 = k0 ? (2.0f * sacc[2] - q1 - d0) : NEGV;
                float s11 = k1 ? (2.0f * sacc[3] - q1 - d1) : NEGV;
                lm0 = fmaxf(lm0, fmaxf(s00, s01));
                lm1 = fmaxf(lm1, fmaxf(s10, s11));
            }
        }
        __syncthreads();   // Dbf/rs reuse next tile
    }

    // Reduce lm over t (4 lanes) -> qpart[q][warp>>1]
    lm0 = fmaxf(lm0, __shfl_xor_sync(0xffffffffu, lm0, 1));
    lm0 = fmaxf(lm0, __shfl_xor_sync(0xffffffffu, lm0, 2));
    lm1 = fmaxf(lm1, __shfl_xor_sync(0xffffffffu, lm1, 1));
    lm1 = fmaxf(lm1, __shfl_xor_sync(0xffffffffu, lm1, 2));
    if (t == 0) {
        int wc = warp >> 1;
        qpart[(mq + g) * 4 + wc]     = lm0;
        qpart[(mq + g + 8) * 4 + wc] = lm1;
    }
    __syncthreads();

    if (tid < 32) {
        float v = NEGV;
#pragma unroll
        for (int j = 0; j < 4; j++) v = fmaxf(v, qpart[tid * 4 + j]);
        g_part[bid * QL + tid] = v;
    }
}

// ---------------------------------------------------------------------------
// Kernel 3: combine the two doc-half partials, sum over queries.
// ---------------------------------------------------------------------------
__global__ void reduce_kernel(float* __restrict__ out)
{
    const int b = blockIdx.x;
    const int q = threadIdx.x;
    float v = fmaxf(g_part[(2 * b) * QL + q], g_part[(2 * b + 1) * QL + q]);
#pragma unroll
    for (int o = 16; o >= 1; o >>= 1) v += __shfl_xor_sync(0xffffffffu, v, o, 32);
    if (q == 0) out[b] = v;
}

// ---------------------------------------------------------------------------
extern "C" void kernel_launch(void* const* d_in, const int* in_sizes, int n_in,
                              void* d_out, int out_size)
{
    const float* Qe   = (const float*)d_in[0];  // [128,32,768]
    const float* De   = (const float*)d_in[1];  // [128,1024,768]
    const int*   ids  = (const int*)  d_in[2];  // [128,1024]
    const int*   attn = (const int*)  d_in[3];  // [128,1024]
    const float* W    = (const float*)d_in[4];  // [128,768]
    float*       out  = (float*)d_out;          // [128]

    wconv_kernel<<<(DIMD * HH) / (256 * 4), 256>>>(W);
    q_proj_kernel<<<BB, 256>>>(Qe, W);

    cudaFuncSetAttribute(score_kernel, cudaFuncAttributeMaxDynamicSharedMemorySize,
                         SM_TOTAL);
    score_kernel<<<2 * BB, 256, SM_TOTAL>>>(De, ids, attn);

    reduce_kernel<<<BB, 32>>>(out);
}

// round 11
// speedup vs baseline: 1.5005x; 1.3611x over previous
#include <cuda_runtime.h>
#include <cuda_bf16.h>
#include <math.h>
#include <stdint.h>

// Problem constants
#define BB   128
#define QL   32
#define DL   1024
#define HH   768
#define DIMD 128
#define NEGV (-100000.0f)

// Scratch
__device__ float g_Qn[BB * QL * DIMD];
__device__ float g_qsq[BB * QL];
__device__ __nv_bfloat16 g_Wbf[DIMD * HH];   // bf16 copy of W

// ---------------------------------------------------------------------------
// Helpers (base-ISA sm_80+)
// ---------------------------------------------------------------------------
__device__ __forceinline__ unsigned smem_u32(const void* p) {
    return (unsigned)__cvta_generic_to_shared(p);
}
__device__ __forceinline__ void cp_async16(unsigned dst, const void* src) {
    asm volatile("cp.async.cg.shared.global [%0], [%1], 16;\n" :: "r"(dst), "l"(src));
}
__device__ __forceinline__ void cp_commit() {
    asm volatile("cp.async.commit_group;\n" ::: "memory");
}
__device__ __forceinline__ void cp_wait2() {
    asm volatile("cp.async.wait_group 2;\n" ::: "memory");
}
__device__ __forceinline__ uint32_t f2bf2(float lo, float hi) {
    uint32_t r;
    asm("cvt.rn.bf16x2.f32 %0, %1, %2;" : "=r"(r) : "f"(hi), "f"(lo));
    return r;
}
__device__ __forceinline__ void ldsm_x4(uint32_t* r, uint32_t addr) {
    asm volatile("ldmatrix.sync.aligned.m8n8.x4.shared.b16 {%0,%1,%2,%3}, [%4];"
                 : "=r"(r[0]), "=r"(r[1]), "=r"(r[2]), "=r"(r[3]) : "r"(addr));
}
__device__ __forceinline__ void sts128(uint32_t addr, uint32_t r0, uint32_t r1,
                                       uint32_t r2, uint32_t r3) {
    asm volatile("st.shared.v4.b32 [%0], {%1,%2,%3,%4};"
                 :: "r"(addr), "r"(r0), "r"(r1), "r"(r2), "r"(r3) : "memory");
}
__device__ __forceinline__ void sts32(uint32_t addr, uint32_t r0) {
    asm volatile("st.shared.b32 [%0], %1;" :: "r"(addr), "r"(r0) : "memory");
}
__device__ __forceinline__ void mma_bf16(float* c, const uint32_t* a, const uint32_t* b) {
    asm volatile(
        "mma.sync.aligned.m16n8k16.row.col.f32.bf16.bf16.f32 "
        "{%0,%1,%2,%3}, {%4,%5,%6,%7}, {%8,%9}, {%0,%1,%2,%3};"
        : "+f"(c[0]), "+f"(c[1]), "+f"(c[2]), "+f"(c[3])
        : "r"(a[0]), "r"(a[1]), "r"(a[2]), "r"(a[3]), "r"(b[0]), "r"(b[1]));
}

// ---------------------------------------------------------------------------
// Kernel 0: W fp32 -> bf16
// ---------------------------------------------------------------------------
__global__ void wconv_kernel(const float* __restrict__ W)
{
    int i = blockIdx.x * 256 + threadIdx.x;
    float4 v = *(const float4*)(W + (size_t)i * 4);
    *(uint2*)((char*)g_Wbf + (size_t)i * 8) = make_uint2(f2bf2(v.x, v.y), f2bf2(v.z, v.w));
}

// ---------------------------------------------------------------------------
// Kernel 1: Q projection + L2 normalize (fp32). 128 CTAs, 256 thr.
// ---------------------------------------------------------------------------
__global__ __launch_bounds__(256, 1)
void q_proj_kernel(const float* __restrict__ Qe, const float* __restrict__ W)
{
    __shared__ float As[32 * 33];
    __shared__ float Ws[32 * 132];

    const int b   = blockIdx.x;
    const int tid = threadIdx.x;
    const int tx  = tid & 15;
    const int ty  = tid >> 4;
    const float* A = Qe + (size_t)b * QL * HH;

    float acc[2][8];
#pragma unroll
    for (int i = 0; i < 2; i++)
#pragma unroll
        for (int j = 0; j < 8; j++) acc[i][j] = 0.0f;

    for (int kk = 0; kk < HH; kk += 32) {
        __syncthreads();
        {
            int r  = tid >> 3;
            int c4 = tid & 7;
            float4 v = *(const float4*)(A + (size_t)r * HH + kk + c4 * 4);
            As[(c4 * 4 + 0) * 33 + r] = v.x;
            As[(c4 * 4 + 1) * 33 + r] = v.y;
            As[(c4 * 4 + 2) * 33 + r] = v.z;
            As[(c4 * 4 + 3) * 33 + r] = v.w;
        }
#pragma unroll
        for (int l = 0; l < 4; l++) {
            int lin = tid + l * 256;
            int r   = lin >> 3;
            int c4  = lin & 7;
            float4 v = *(const float4*)(W + (size_t)r * HH + kk + c4 * 4);
            Ws[(c4 * 4 + 0) * 132 + r] = v.x;
            Ws[(c4 * 4 + 1) * 132 + r] = v.y;
            Ws[(c4 * 4 + 2) * 132 + r] = v.z;
            Ws[(c4 * 4 + 3) * 132 + r] = v.w;
        }
        __syncthreads();

#pragma unroll 8
        for (int k = 0; k < 32; k++) {
            float a0 = As[k * 33 + ty * 2];
            float a1 = As[k * 33 + ty * 2 + 1];
            float4 w0 = *(const float4*)&Ws[k * 132 + tx * 8];
            float4 w1 = *(const float4*)&Ws[k * 132 + tx * 8 + 4];
            float w[8] = {w0.x, w0.y, w0.z, w0.w, w1.x, w1.y, w1.z, w1.w};
#pragma unroll
            for (int j = 0; j < 8; j++) {
                acc[0][j] = fmaf(a0, w[j], acc[0][j]);
                acc[1][j] = fmaf(a1, w[j], acc[1][j]);
            }
        }
    }

#pragma unroll
    for (int i = 0; i < 2; i++) {
        float s = 0.0f;
#pragma unroll
        for (int j = 0; j < 8; j++) s += acc[i][j] * acc[i][j];
#pragma unroll
        for (int o = 8; o >= 1; o >>= 1) s += __shfl_xor_sync(0xffffffffu, s, o, 16);
        float inv = 1.0f / fmaxf(sqrtf(s), 1e-12f);
        int   m   = ty * 2 + i;
#pragma unroll
        for (int j = 0; j < 8; j++) acc[i][j] *= inv;
        *(float4*)(g_Qn + ((size_t)b * QL + m) * DIMD + tx * 8) =
            make_float4(acc[i][0], acc[i][1], acc[i][2], acc[i][3]);
        *(float4*)(g_Qn + ((size_t)b * QL + m) * DIMD + tx * 8 + 4) =
            make_float4(acc[i][4], acc[i][5], acc[i][6], acc[i][7]);
        if (tx == 0) g_qsq[b * QL + m] = s * inv * inv;
    }
}

// ---------------------------------------------------------------------------
// Kernel 2: fused D projection + mask + normalize + MMA scoring.
// 128 CTAs (one batch), 512 threads. Doc tile 128x128, warp tile 32x32,
// KC=64. A: register-prefetch distance 2. W: 4 smem buffers, distance 3,
// with the cp.async issued AFTER __syncthreads so the target buffer's last
// reader (MMA s-1) is provably done.
//
// SMEM bytes:
//   Qbf   0       8704    (32 x 128 bf16, stride 272)
//   Dbf   8704    34816   (128 x 128 bf16, stride 272)
//   A0    43520   18432   (128 x 64 bf16, stride 144)
//   A1    61952   18432
//   W0    80384   18432
//   W1    98816   18432
//   W2    117248  18432
//   W3    135680  18432
//   rs    154112  2048    (4 x 128 f32)
//   dsq   156160  512
//   qsq   156672  128
//   qpart 156800  1024    (32 x 8 f32)
//   total 157824
// ---------------------------------------------------------------------------
#define SM_QBF   0
#define SM_DBF   8704
#define SM_A0    43520
#define SM_A1    61952
#define SM_W0    80384
#define SM_W1    98816
#define SM_W2    117248
#define SM_W3    135680
#define SM_RS    154112
#define SM_DSQ   156160
#define SM_QSQ   156672
#define SM_QPART 156800
#define SM_TOTAL 157824

#define RSTR    144          // A/W row stride (64 bf16 + pad)
#define QSTR    272          // Qbf/Dbf row stride (128 bf16 + pad)
#define KC      64
#define NCHUNK  (HH / KC)    // 12

__global__ __launch_bounds__(512, 1)
void score_kernel(const float* __restrict__ Demb,
                  const int*   __restrict__ ids,
                  const int*   __restrict__ attn,
                  float*       __restrict__ out)
{
    extern __shared__ char smc[];
    float* rs    = (float*)(smc + SM_RS);
    float* dsq   = (float*)(smc + SM_DSQ);
    float* qsq   = (float*)(smc + SM_QSQ);
    float* qpart = (float*)(smc + SM_QPART);

    const uint32_t base = smem_u32(smc);

    const int b    = blockIdx.x;
    const int tid  = threadIdx.x;
    const int lane = tid & 31;
    const int warp = tid >> 5;
    const int warpM = warp >> 2;       // 0..3 -> rows warpM*32..+31
    const int warpN = warp & 3;        // 0..3 -> cols warpN*32..+31
    const int g    = lane >> 2;        // 0..7
    const int t    = lane & 3;         // 0..3

    // A staging: thread owns rows r0 and r0+64, 8 floats each (c8*8..+7)
    const int r0 = tid >> 3;           // 0..63
    const int c8 = tid & 7;

    // Main-GEMM ldmatrix offsets
    const uint32_t aoff = (uint32_t)(warpM * 32 + (lane & 15)) * RSTR
                        + ((lane >> 4) & 1) * 16;
    const uint32_t boff = (uint32_t)(warpN * 32 + ((lane >> 4) & 1) * 8 + (lane & 7)) * RSTR
                        + ((lane >> 3) & 1) * 16;
    const uint32_t Au[2]   = {base + SM_A0 + aoff, base + SM_A1 + aoff};
    const uint32_t Adst[2] = {base + SM_A0, base + SM_A1};
    const uint32_t Wu[4]   = {base + SM_W0 + boff, base + SM_W1 + boff,
                              base + SM_W2 + boff, base + SM_W3 + boff};
    const uint32_t Wdst[4] = {base + SM_W0, base + SM_W1, base + SM_W2, base + SM_W3};

    // Score-GEMM offsets: each warp does m16 x two n8 tiles (n0 and n0+64)
    const int mq = (warp & 1) * 16;
    const int n0 = (warp >> 1) * 8;
    const uint32_t qa = base + SM_QBF + (uint32_t)(mq + (lane & 15)) * QSTR
                      + ((lane >> 4) & 1) * 16;
    const uint32_t da0 = base + SM_DBF + (uint32_t)(n0 + (lane & 7)) * QSTR
                       + ((lane >> 3) & 3) * 16;
    const uint32_t da1 = da0 + 64 * QSTR;

    // Stage Qbf (fp32 g_Qn -> bf16 smem) + qsq
    if (tid < 256) {
        int row = tid >> 3, sg = tid & 7;
        const float* p = g_Qn + ((size_t)b * QL + row) * DIMD + sg * 16;
        float4 v0 = *(const float4*)(p);
        float4 v1 = *(const float4*)(p + 4);
        float4 v2 = *(const float4*)(p + 8);
        float4 v3 = *(const float4*)(p + 12);
        uint32_t addr = base + SM_QBF + row * QSTR + sg * 32;
        sts128(addr,      f2bf2(v0.x, v0.y), f2bf2(v0.z, v0.w),
                          f2bf2(v1.x, v1.y), f2bf2(v1.z, v1.w));
        sts128(addr + 16, f2bf2(v2.x, v2.y), f2bf2(v2.z, v2.w),
                          f2bf2(v3.x, v3.y), f2bf2(v3.z, v3.w));
    }
    if (tid < 32) qsq[tid] = g_qsq[b * QL + tid];

    float lm0 = NEGV, lm1 = NEGV;      // running max for query rows mq+g, mq+g+8

    for (int t0 = 0; t0 < DL; t0 += 128) {
        const float* a0p = Demb + ((size_t)b * DL + t0 + r0) * HH + c8 * 8;
        const float* a1p = a0p + (size_t)64 * HH;

        float acc[2][4][4];
#pragma unroll
        for (int m = 0; m < 2; m++)
#pragma unroll
            for (int n = 0; n < 4; n++)
#pragma unroll
                for (int r = 0; r < 4; r++) acc[m][n][r] = 0.0f;

        // Prologue: LDG A chunks 0,1 -> regs; cp.async W chunks 0,1,2 (3 groups)
        float4 ra[2][4];
#pragma unroll
        for (int c = 0; c < 2; c++) {
            ra[c][0] = *(const float4*)(a0p + c * KC);
            ra[c][1] = *(const float4*)(a0p + c * KC + 4);
            ra[c][2] = *(const float4*)(a1p + c * KC);
            ra[c][3] = *(const float4*)(a1p + c * KC + 4);
        }
#pragma unroll
        for (int c = 0; c < 3; c++) {
#pragma unroll
            for (int l = 0; l < 2; l++) {
                int lin = tid + l * 512;
                int wr  = lin >> 3;
                int c16 = lin & 7;
                cp_async16(Wdst[c] + wr * RSTR + c16 * 16,
                           (const char*)g_Wbf + (size_t)wr * (HH * 2)
                               + c * (KC * 2) + c16 * 16);
            }
            cp_commit();
        }

        for (int s = 0; s < NCHUNK; s++) {
            // 1. STS chunk s A (regs -> bf16 smem). A[s&1] safe: fenced from
            //    MMA(s-2) readers by sync(s-1).
            const uint32_t ab = Adst[s & 1] + (uint32_t)r0 * RSTR + c8 * 16;
            sts128(ab,
                   f2bf2(ra[s & 1][0].x, ra[s & 1][0].y), f2bf2(ra[s & 1][0].z, ra[s & 1][0].w),
                   f2bf2(ra[s & 1][1].x, ra[s & 1][1].y), f2bf2(ra[s & 1][1].z, ra[s & 1][1].w));
            sts128(ab + 64 * RSTR,
                   f2bf2(ra[s & 1][2].x, ra[s & 1][2].y), f2bf2(ra[s & 1][2].z, ra[s & 1][2].w),
                   f2bf2(ra[s & 1][3].x, ra[s & 1][3].y), f2bf2(ra[s & 1][3].z, ra[s & 1][3].w));

            // 2. LDG chunk s+2 -> same reg buffer (distance 2; per-thread regs)
            if (s + 2 < NCHUNK) {
                ra[s & 1][0] = *(const float4*)(a0p + (s + 2) * KC);
                ra[s & 1][1] = *(const float4*)(a0p + (s + 2) * KC + 4);
                ra[s & 1][2] = *(const float4*)(a1p + (s + 2) * KC);
                ra[s & 1][3] = *(const float4*)(a1p + (s + 2) * KC + 4);
            }

            // 3. Wait W chunk s (2 newer groups outstanding), then barrier.
            cp_wait2();
            __syncthreads();

            // 4. NOW safe to overwrite W[(s+3)&3] = W[(s-1)&3]: every warp
            //    passed the barrier, so MMA(s-1) is complete block-wide.
            if (s + 3 < NCHUNK) {
                uint32_t wdst = Wdst[(s + 3) & 3];
#pragma unroll
                for (int l = 0; l < 2; l++) {
                    int lin = tid + l * 512;
                    int wr  = lin >> 3;
                    int c16 = lin & 7;
                    cp_async16(wdst + wr * RSTR + c16 * 16,
                               (const char*)g_Wbf + (size_t)wr * (HH * 2)
                                   + (s + 3) * (KC * 2) + c16 * 16);
                }
            }
            cp_commit();   // unconditional: keeps group indexing uniform

            // 5. MMA chunk s
            const uint32_t au = Au[s & 1];
            const uint32_t wb = Wu[s & 3];
#pragma unroll
            for (int kb = 0; kb < 4; kb++) {
                uint32_t a0[4], a1[4], b0[4], b1[4];
                ldsm_x4(a0, au + kb * 32);
                ldsm_x4(a1, au + 16 * RSTR + kb * 32);
                ldsm_x4(b0, wb + kb * 32);
                ldsm_x4(b1, wb + 16 * RSTR + kb * 32);
                mma_bf16(acc[0][0], a0, b0);
                mma_bf16(acc[0][1], a0, b0 + 2);
                mma_bf16(acc[0][2], a0, b1);
                mma_bf16(acc[0][3], a0, b1 + 2);
                mma_bf16(acc[1][0], a1, b0);
                mma_bf16(acc[1][1], a1, b0 + 2);
                mma_bf16(acc[1][2], a1, b1);
                mma_bf16(acc[1][3], a1, b1 + 2);
            }
        }

        // ---- Epilogue: mask + row-norm partials ----
#pragma unroll
        for (int m = 0; m < 2; m++) {
#pragma unroll
            for (int h = 0; h < 2; h++) {
                int row = warpM * 32 + m * 16 + h * 8 + g;
                bool z  = (ids[b * DL + t0 + row] == 0);
                float s = 0.0f;
#pragma unroll
                for (int n = 0; n < 4; n++) {
                    if (z) { acc[m][n][h * 2] = 0.0f; acc[m][n][h * 2 + 1] = 0.0f; }
                    float x = acc[m][n][h * 2];
                    float y = acc[m][n][h * 2 + 1];
                    s += x * x + y * y;
                }
                s += __shfl_xor_sync(0xffffffffu, s, 1, 4);
                s += __shfl_xor_sync(0xffffffffu, s, 2, 4);
                if (t == 0) rs[warpN * 128 + row] = s;
            }
        }
        __syncthreads();

        // ---- Normalize -> bf16 Dbf + dsq ----
#pragma unroll
        for (int m = 0; m < 2; m++) {
#pragma unroll
            for (int h = 0; h < 2; h++) {
                int row   = warpM * 32 + m * 16 + h * 8 + g;
                float st  = rs[row] + rs[128 + row] + rs[256 + row] + rs[384 + row];
                float inv = 1.0f / fmaxf(sqrtf(st), 1e-12f);
#pragma unroll
                for (int n = 0; n < 4; n++) {
                    int col = warpN * 32 + n * 8 + t * 2;
                    uint32_t pk = f2bf2(acc[m][n][h * 2] * inv, acc[m][n][h * 2 + 1] * inv);
                    sts32(base + SM_DBF + (uint32_t)row * QSTR + col * 2, pk);
                }
                if (warpN == 0 && t == 0) dsq[row] = st * inv * inv;
            }
        }
        __syncthreads();

        // ---- Score GEMM: S = Q . D^T, two n8 tiles per warp (n0, n0+64) ----
        {
            const float q0 = qsq[mq + g], q1 = qsq[mq + g + 8];
#pragma unroll
            for (int half = 0; half < 2; half++) {
                const uint32_t da = half ? da1 : da0;
                float sacc[4] = {0.0f, 0.0f, 0.0f, 0.0f};
#pragma unroll
                for (int kb = 0; kb < 8; kb += 2) {
                    uint32_t aA[4], aB[4], bb[4];
                    ldsm_x4(aA, qa + kb * 32);
                    ldsm_x4(aB, qa + (kb + 1) * 32);
                    ldsm_x4(bb, da + kb * 32);
                    mma_bf16(sacc, aA, bb);
                    mma_bf16(sacc, aB, bb + 2);
                }
                const int col0 = n0 + half * 64 + t * 2;
                const int col1 = col0 + 1;
                const bool k0  = attn[b * DL + t0 + col0] != 0;
                const bool k1  = attn[b * DL + t0 + col1] != 0;
                const float d0 = dsq[col0], d1 = dsq[col1];
                float s00 = k0 ? (2.0f * sacc[0] - q0 - d0) : NEGV;
                float s01 = k1 ? (2.0f * sacc[1] - q0 - d1) : NEGV;
                float s10 = k0 ? (2.0f * sacc[2] - q1 - d0) : NEGV;
                float s11 = k1 ? (2.0f * sacc[3] - q1 - d1) : NEGV;
                lm0 = fmaxf(lm0, fmaxf(s00, s01));
                lm1 = fmaxf(lm1, fmaxf(s10, s11));
            }
        }
        __syncthreads();   // Dbf/rs reuse next tile
    }

    // Reduce lm over t (4 lanes), write per-warp partials
    lm0 = fmaxf(lm0, __shfl_xor_sync(0xffffffffu, lm0, 1));
    lm0 = fmaxf(lm0, __shfl_xor_sync(0xffffffffu, lm0, 2));
    lm1 = fmaxf(lm1, __shfl_xor_sync(0xffffffffu, lm1, 1));
    lm1 = fmaxf(lm1, __shfl_xor_sync(0xffffffffu, lm1, 2));
    if (t == 0) {
        int wc = warp >> 1;
        qpart[(mq + g) * 8 + wc]     = lm0;
        qpart[(mq + g + 8) * 8 + wc] = lm1;
    }
    __syncthreads();

    if (tid < 32) {
        float v = NEGV;
#pragma unroll
        for (int j = 0; j < 8; j++) v = fmaxf(v, qpart[tid * 8 + j]);
#pragma unroll
        for (int o = 16; o >= 1; o >>= 1) v += __shfl_xor_sync(0xffffffffu, v, o, 32);
        if (tid == 0) out[b] = v;
    }
}

// ---------------------------------------------------------------------------
extern "C" void kernel_launch(void* const* d_in, const int* in_sizes, int n_in,
                              void* d_out, int out_size)
{
    const float* Qe   = (const float*)d_in[0];  // [128,32,768]
    const float* De   = (const float*)d_in[1];  // [128,1024,768]
    const int*   ids  = (const int*)  d_in[2];  // [128,1024]
    const int*   attn = (const int*)  d_in[3];  // [128,1024]
    const float* W    = (const float*)d_in[4];  // [128,768]
    float*       out  = (float*)d_out;          // [128]

    wconv_kernel<<<(DIMD * HH) / (256 * 4), 256>>>(W);
    q_proj_kernel<<<BB, 256>>>(Qe, W);

    cudaFuncSetAttribute(score_kernel, cudaFuncAttributeMaxDynamicSharedMemorySize,
                         SM_TOTAL);
    score_kernel<<<BB, 512, SM_TOTAL>>>(De, ids, attn, out);
}

// round 12
// speedup vs baseline: 1.8404x; 1.2266x over previous
#include <cuda_runtime.h>
#include <cuda_bf16.h>
#include <math.h>
#include <stdint.h>

// Problem constants
#define BB   128
#define QL   32
#define DL   1024
#define HH   768
#define DIMD 128
#define NEGV (-100000.0f)

// Scratch
__device__ float g_Qn[BB * QL * DIMD];
__device__ float g_qsq[BB * QL];
__device__ __nv_bfloat16 g_Wbf[DIMD * HH];   // bf16 copy of W
__device__ int g_idx[BB * DL];               // compacted kept-doc indices
__device__ int g_nkeep[BB];                  // kept count per batch

// ---------------------------------------------------------------------------
// Helpers (base-ISA sm_80+)
// ---------------------------------------------------------------------------
__device__ __forceinline__ unsigned smem_u32(const void* p) {
    return (unsigned)__cvta_generic_to_shared(p);
}
__device__ __forceinline__ void cp_async16(unsigned dst, const void* src) {
    asm volatile("cp.async.cg.shared.global [%0], [%1], 16;\n" :: "r"(dst), "l"(src));
}
__device__ __forceinline__ void cp_commit() {
    asm volatile("cp.async.commit_group;\n" ::: "memory");
}
__device__ __forceinline__ void cp_wait2() {
    asm volatile("cp.async.wait_group 2;\n" ::: "memory");
}
__device__ __forceinline__ uint32_t f2bf2(float lo, float hi) {
    uint32_t r;
    asm("cvt.rn.bf16x2.f32 %0, %1, %2;" : "=r"(r) : "f"(hi), "f"(lo));
    return r;
}
__device__ __forceinline__ void ldsm_x4(uint32_t* r, uint32_t addr) {
    asm volatile("ldmatrix.sync.aligned.m8n8.x4.shared.b16 {%0,%1,%2,%3}, [%4];"
                 : "=r"(r[0]), "=r"(r[1]), "=r"(r[2]), "=r"(r[3]) : "r"(addr));
}
__device__ __forceinline__ void sts128(uint32_t addr, uint32_t r0, uint32_t r1,
                                       uint32_t r2, uint32_t r3) {
    asm volatile("st.shared.v4.b32 [%0], {%1,%2,%3,%4};"
                 :: "r"(addr), "r"(r0), "r"(r1), "r"(r2), "r"(r3) : "memory");
}
__device__ __forceinline__ void sts32(uint32_t addr, uint32_t r0) {
    asm volatile("st.shared.b32 [%0], %1;" :: "r"(addr), "r"(r0) : "memory");
}
__device__ __forceinline__ void mma_bf16(float* c, const uint32_t* a, const uint32_t* b) {
    asm volatile(
        "mma.sync.aligned.m16n8k16.row.col.f32.bf16.bf16.f32 "
        "{%0,%1,%2,%3}, {%4,%5,%6,%7}, {%8,%9}, {%0,%1,%2,%3};"
        : "+f"(c[0]), "+f"(c[1]), "+f"(c[2]), "+f"(c[3])
        : "r"(a[0]), "r"(a[1]), "r"(a[2]), "r"(a[3]), "r"(b[0]), "r"(b[1]));
}

// ---------------------------------------------------------------------------
// Kernel 0: W fp32 -> bf16
// ---------------------------------------------------------------------------
__global__ void wconv_kernel(const float* __restrict__ W)
{
    int i = blockIdx.x * 256 + threadIdx.x;
    float4 v = *(const float4*)(W + (size_t)i * 4);
    *(uint2*)((char*)g_Wbf + (size_t)i * 8) = make_uint2(f2bf2(v.x, v.y), f2bf2(v.z, v.w));
}

// ---------------------------------------------------------------------------
// Kernel 0b: compact kept-doc indices per batch (attn != 0).
// Order-scrambled (atomic) — max over docs is order-invariant.
// ---------------------------------------------------------------------------
__global__ void compact_kernel(const int* __restrict__ attn)
{
    __shared__ int cnt;
    const int b = blockIdx.x;
    const int tid = threadIdx.x;
    if (tid == 0) cnt = 0;
    __syncthreads();
    for (int j = tid; j < DL; j += 256) {
        if (attn[b * DL + j] != 0) {
            int p = atomicAdd(&cnt, 1);
            g_idx[b * DL + p] = j;
        }
    }
    __syncthreads();
    if (tid == 0) g_nkeep[b] = cnt;
}

// ---------------------------------------------------------------------------
// Kernel 1: Q projection + L2 normalize (fp32). 128 CTAs, 256 thr.
// ---------------------------------------------------------------------------
__global__ __launch_bounds__(256, 1)
void q_proj_kernel(const float* __restrict__ Qe, const float* __restrict__ W)
{
    __shared__ float As[32 * 33];
    __shared__ float Ws[32 * 132];

    const int b   = blockIdx.x;
    const int tid = threadIdx.x;
    const int tx  = tid & 15;
    const int ty  = tid >> 4;
    const float* A = Qe + (size_t)b * QL * HH;

    float acc[2][8];
#pragma unroll
    for (int i = 0; i < 2; i++)
#pragma unroll
        for (int j = 0; j < 8; j++) acc[i][j] = 0.0f;

    for (int kk = 0; kk < HH; kk += 32) {
        __syncthreads();
        {
            int r  = tid >> 3;
            int c4 = tid & 7;
            float4 v = *(const float4*)(A + (size_t)r * HH + kk + c4 * 4);
            As[(c4 * 4 + 0) * 33 + r] = v.x;
            As[(c4 * 4 + 1) * 33 + r] = v.y;
            As[(c4 * 4 + 2) * 33 + r] = v.z;
            As[(c4 * 4 + 3) * 33 + r] = v.w;
        }
#pragma unroll
        for (int l = 0; l < 4; l++) {
            int lin = tid + l * 256;
            int r   = lin >> 3;
            int c4  = lin & 7;
            float4 v = *(const float4*)(W + (size_t)r * HH + kk + c4 * 4);
            Ws[(c4 * 4 + 0) * 132 + r] = v.x;
            Ws[(c4 * 4 + 1) * 132 + r] = v.y;
            Ws[(c4 * 4 + 2) * 132 + r] = v.z;
            Ws[(c4 * 4 + 3) * 132 + r] = v.w;
        }
        __syncthreads();

#pragma unroll 8
        for (int k = 0; k < 32; k++) {
            float a0 = As[k * 33 + ty * 2];
            float a1 = As[k * 33 + ty * 2 + 1];
            float4 w0 = *(const float4*)&Ws[k * 132 + tx * 8];
            float4 w1 = *(const float4*)&Ws[k * 132 + tx * 8 + 4];
            float w[8] = {w0.x, w0.y, w0.z, w0.w, w1.x, w1.y, w1.z, w1.w};
#pragma unroll
            for (int j = 0; j < 8; j++) {
                acc[0][j] = fmaf(a0, w[j], acc[0][j]);
                acc[1][j] = fmaf(a1, w[j], acc[1][j]);
            }
        }
    }

#pragma unroll
    for (int i = 0; i < 2; i++) {
        float s = 0.0f;
#pragma unroll
        for (int j = 0; j < 8; j++) s += acc[i][j] * acc[i][j];
#pragma unroll
        for (int o = 8; o >= 1; o >>= 1) s += __shfl_xor_sync(0xffffffffu, s, o, 16);
        float inv = 1.0f / fmaxf(sqrtf(s), 1e-12f);
        int   m   = ty * 2 + i;
#pragma unroll
        for (int j = 0; j < 8; j++) acc[i][j] *= inv;
        *(float4*)(g_Qn + ((size_t)b * QL + m) * DIMD + tx * 8) =
            make_float4(acc[i][0], acc[i][1], acc[i][2], acc[i][3]);
        *(float4*)(g_Qn + ((size_t)b * QL + m) * DIMD + tx * 8 + 4) =
            make_float4(acc[i][4], acc[i][5], acc[i][6], acc[i][7]);
        if (tx == 0) g_qsq[b * QL + m] = s * inv * inv;
    }
}

// ---------------------------------------------------------------------------
// Kernel 2: fused D projection + mask + normalize + MMA scoring over the
// COMPACTED kept docs only (~half the tiles). 128 CTAs, 512 threads.
// Doc tile 128x128, warp tile 32x32, KC=64, A reg-prefetch d2, W 4-buf d3.
// ---------------------------------------------------------------------------
#define SM_QBF   0
#define SM_DBF   8704
#define SM_A0    43520
#define SM_A1    61952
#define SM_W0    80384
#define SM_W1    98816
#define SM_W2    117248
#define SM_W3    135680
#define SM_RS    154112
#define SM_DSQ   156160
#define SM_QSQ   156672
#define SM_QPART 156800
#define SM_TOTAL 157824

#define RSTR    144          // A/W row stride (64 bf16 + pad)
#define QSTR    272          // Qbf/Dbf row stride (128 bf16 + pad)
#define KC      64
#define NCHUNK  (HH / KC)    // 12

__global__ __launch_bounds__(512, 1)
void score_kernel(const float* __restrict__ Demb,
                  const int*   __restrict__ ids,
                  float*       __restrict__ out)
{
    extern __shared__ char smc[];
    float* rs    = (float*)(smc + SM_RS);
    float* dsq   = (float*)(smc + SM_DSQ);
    float* qsq   = (float*)(smc + SM_QSQ);
    float* qpart = (float*)(smc + SM_QPART);

    const uint32_t base = smem_u32(smc);

    const int b    = blockIdx.x;
    const int tid  = threadIdx.x;
    const int lane = tid & 31;
    const int warp = tid >> 5;
    const int warpM = warp >> 2;       // 0..3 -> rows warpM*32..+31
    const int warpN = warp & 3;        // 0..3 -> cols warpN*32..+31
    const int g    = lane >> 2;        // 0..7
    const int t    = lane & 3;         // 0..3

    // A staging: thread owns compacted rows (t0+r0) and (t0+r0+64)
    const int r0 = tid >> 3;           // 0..63
    const int c8 = tid & 7;

    // Main-GEMM ldmatrix offsets
    const uint32_t aoff = (uint32_t)(warpM * 32 + (lane & 15)) * RSTR
                        + ((lane >> 4) & 1) * 16;
    const uint32_t boff = (uint32_t)(warpN * 32 + ((lane >> 4) & 1) * 8 + (lane & 7)) * RSTR
                        + ((lane >> 3) & 1) * 16;
    const uint32_t Au[2]   = {base + SM_A0 + aoff, base + SM_A1 + aoff};
    const uint32_t Adst[2] = {base + SM_A0, base + SM_A1};
    const uint32_t Wu[4]   = {base + SM_W0 + boff, base + SM_W1 + boff,
                              base + SM_W2 + boff, base + SM_W3 + boff};
    const uint32_t Wdst[4] = {base + SM_W0, base + SM_W1, base + SM_W2, base + SM_W3};

    // Score-GEMM offsets: each warp does m16 x two n8 tiles (n0 and n0+64)
    const int mq = (warp & 1) * 16;
    const int n0 = (warp >> 1) * 8;
    const uint32_t qa = base + SM_QBF + (uint32_t)(mq + (lane & 15)) * QSTR
                      + ((lane >> 4) & 1) * 16;
    const uint32_t da0 = base + SM_DBF + (uint32_t)(n0 + (lane & 7)) * QSTR
                       + ((lane >> 3) & 3) * 16;
    const uint32_t da1 = da0 + 64 * QSTR;

    // Stage Qbf (fp32 g_Qn -> bf16 smem) + qsq
    if (tid < 256) {
        int row = tid >> 3, sg = tid & 7;
        const float* p = g_Qn + ((size_t)b * QL + row) * DIMD + sg * 16;
        float4 v0 = *(const float4*)(p);
        float4 v1 = *(const float4*)(p + 4);
        float4 v2 = *(const float4*)(p + 8);
        float4 v3 = *(const float4*)(p + 12);
        uint32_t addr = base + SM_QBF + row * QSTR + sg * 32;
        sts128(addr,      f2bf2(v0.x, v0.y), f2bf2(v0.z, v0.w),
                          f2bf2(v1.x, v1.y), f2bf2(v1.z, v1.w));
        sts128(addr + 16, f2bf2(v2.x, v2.y), f2bf2(v2.z, v2.w),
                          f2bf2(v3.x, v3.y), f2bf2(v3.z, v3.w));
    }
    if (tid < 32) qsq[tid] = g_qsq[b * QL + tid];

    const int nk = g_nkeep[b];
    const int ntiles = (nk + 127) >> 7;
    const int* idxb = g_idx + b * DL;

    float lm0 = NEGV, lm1 = NEGV;      // running max for query rows mq+g, mq+g+8

    for (int ti = 0; ti < ntiles; ti++) {
        const int t0 = ti * 128;

        // Gather source rows for this thread's two staged rows
        const int rg0 = t0 + r0;
        const int rg1 = t0 + r0 + 64;
        const int i0  = (rg0 < nk) ? idxb[rg0] : 0;
        const int i1  = (rg1 < nk) ? idxb[rg1] : 0;
        const float* a0p = Demb + ((size_t)b * DL + i0) * HH + c8 * 8;
        const float* a1p = Demb + ((size_t)b * DL + i1) * HH + c8 * 8;

        float acc[2][4][4];
#pragma unroll
        for (int m = 0; m < 2; m++)
#pragma unroll
            for (int n = 0; n < 4; n++)
#pragma unroll
                for (int r = 0; r < 4; r++) acc[m][n][r] = 0.0f;

        // Prologue: LDG A chunks 0,1 -> regs; cp.async W chunks 0,1,2
        float4 ra[2][4];
#pragma unroll
        for (int c = 0; c < 2; c++) {
            ra[c][0] = *(const float4*)(a0p + c * KC);
            ra[c][1] = *(const float4*)(a0p + c * KC + 4);
            ra[c][2] = *(const float4*)(a1p + c * KC);
            ra[c][3] = *(const float4*)(a1p + c * KC + 4);
        }
#pragma unroll
        for (int c = 0; c < 3; c++) {
#pragma unroll
            for (int l = 0; l < 2; l++) {
                int lin = tid + l * 512;
                int wr  = lin >> 3;
                int c16 = lin & 7;
                cp_async16(Wdst[c] + wr * RSTR + c16 * 16,
                           (const char*)g_Wbf + (size_t)wr * (HH * 2)
                               + c * (KC * 2) + c16 * 16);
            }
            cp_commit();
        }

        for (int s = 0; s < NCHUNK; s++) {
            // 1. STS chunk s A (regs -> bf16 smem)
            const uint32_t ab = Adst[s & 1] + (uint32_t)r0 * RSTR + c8 * 16;
            sts128(ab,
                   f2bf2(ra[s & 1][0].x, ra[s & 1][0].y), f2bf2(ra[s & 1][0].z, ra[s & 1][0].w),
                   f2bf2(ra[s & 1][1].x, ra[s & 1][1].y), f2bf2(ra[s & 1][1].z, ra[s & 1][1].w));
            sts128(ab + 64 * RSTR,
                   f2bf2(ra[s & 1][2].x, ra[s & 1][2].y), f2bf2(ra[s & 1][2].z, ra[s & 1][2].w),
                   f2bf2(ra[s & 1][3].x, ra[s & 1][3].y), f2bf2(ra[s & 1][3].z, ra[s & 1][3].w));

            // 2. LDG chunk s+2 (distance 2)
            if (s + 2 < NCHUNK) {
                ra[s & 1][0] = *(const float4*)(a0p + (s + 2) * KC);
                ra[s & 1][1] = *(const float4*)(a0p + (s + 2) * KC + 4);
                ra[s & 1][2] = *(const float4*)(a1p + (s + 2) * KC);
                ra[s & 1][3] = *(const float4*)(a1p + (s + 2) * KC + 4);
            }

            // 3. Wait W chunk s, then barrier
            cp_wait2();
            __syncthreads();

            // 4. cp.async W chunk s+3 (safe after barrier: MMA s-1 done)
            if (s + 3 < NCHUNK) {
                uint32_t wdst = Wdst[(s + 3) & 3];
#pragma unroll
                for (int l = 0; l < 2; l++) {
                    int lin = tid + l * 512;
                    int wr  = lin >> 3;
                    int c16 = lin & 7;
                    cp_async16(wdst + wr * RSTR + c16 * 16,
                               (const char*)g_Wbf + (size_t)wr * (HH * 2)
                                   + (s + 3) * (KC * 2) + c16 * 16);
                }
            }
            cp_commit();   // unconditional: uniform group indexing

            // 5. MMA chunk s
            const uint32_t au = Au[s & 1];
            const uint32_t wb = Wu[s & 3];
#pragma unroll
            for (int kb = 0; kb < 4; kb++) {
                uint32_t a0[4], a1[4], b0[4], b1[4];
                ldsm_x4(a0, au + kb * 32);
                ldsm_x4(a1, au + 16 * RSTR + kb * 32);
                ldsm_x4(b0, wb + kb * 32);
                ldsm_x4(b1, wb + 16 * RSTR + kb * 32);
                mma_bf16(acc[0][0], a0, b0);
                mma_bf16(acc[0][1], a0, b0 + 2);
                mma_bf16(acc[0][2], a0, b1);
                mma_bf16(acc[0][3], a0, b1 + 2);
                mma_bf16(acc[1][0], a1, b0);
                mma_bf16(acc[1][1], a1, b0 + 2);
                mma_bf16(acc[1][2], a1, b1);
                mma_bf16(acc[1][3], a1, b1 + 2);
            }
        }

        // ---- Epilogue: ids mask (via index) + row-norm partials ----
#pragma unroll
        for (int m = 0; m < 2; m++) {
#pragma unroll
            for (int h = 0; h < 2; h++) {
                int row = warpM * 32 + m * 16 + h * 8 + g;
                int rg  = t0 + row;
                int di  = (rg < nk) ? idxb[rg] : 0;
                bool z  = (ids[b * DL + di] == 0);
                float s = 0.0f;
#pragma unroll
                for (int n = 0; n < 4; n++) {
                    if (z) { acc[m][n][h * 2] = 0.0f; acc[m][n][h * 2 + 1] = 0.0f; }
                    float x = acc[m][n][h * 2];
                    float y = acc[m][n][h * 2 + 1];
                    s += x * x + y * y;
                }
                s += __shfl_xor_sync(0xffffffffu, s, 1, 4);
                s += __shfl_xor_sync(0xffffffffu, s, 2, 4);
                if (t == 0) rs[warpN * 128 + row] = s;
            }
        }
        __syncthreads();

        // ---- Normalize -> bf16 Dbf + dsq ----
#pragma unroll
        for (int m = 0; m < 2; m++) {
#pragma unroll
            for (int h = 0; h < 2; h++) {
                int row   = warpM * 32 + m * 16 + h * 8 + g;
                float st  = rs[row] + rs[128 + row] + rs[256 + row] + rs[384 + row];
                float inv = 1.0f / fmaxf(sqrtf(st), 1e-12f);
#pragma unroll
                for (int n = 0; n < 4; n++) {
                    int col = warpN * 32 + n * 8 + t * 2;
                    uint32_t pk = f2bf2(acc[m][n][h * 2] * inv, acc[m][n][h * 2 + 1] * inv);
                    sts32(base + SM_DBF + (uint32_t)row * QSTR + col * 2, pk);
                }
                if (warpN == 0 && t == 0) dsq[row] = st * inv * inv;
            }
        }
        __syncthreads();

        // ---- Score GEMM: S = Q . D^T; validity = compacted col < nk ----
        {
            const float q0 = qsq[mq + g], q1 = qsq[mq + g + 8];
#pragma unroll
            for (int half = 0; half < 2; half++) {
                const uint32_t da = half ? da1 : da0;
                float sacc[4] = {0.0f, 0.0f, 0.0f, 0.0f};
#pragma unroll
                for (int kb = 0; kb < 8; kb += 2) {
                    uint32_t aA[4], aB[4], bb[4];
                    ldsm_x4(aA, qa + kb * 32);
                    ldsm_x4(aB, qa + (kb + 1) * 32);
                    ldsm_x4(bb, da + kb * 32);
                    mma_bf16(sacc, aA, bb);
                    mma_bf16(sacc, aB, bb + 2);
                }
                const int col0 = n0 + half * 64 + t * 2;
                const int col1 = col0 + 1;
                const bool k0  = (t0 + col0) < nk;
                const bool k1  = (t0 + col1) < nk;
                const float d0 = dsq[col0], d1 = dsq[col1];
                float s00 = k0 ? (2.0f * sacc[0] - q0 - d0) : NEGV;
                float s01 = k1 ? (2.0f * sacc[1] - q0 - d1) : NEGV;
                float s10 = k0 ? (2.0f * sacc[2] - q1 - d0) : NEGV;
                float s11 = k1 ? (2.0f * sacc[3] - q1 - d1) : NEGV;
                lm0 = fmaxf(lm0, fmaxf(s00, s01));
                lm1 = fmaxf(lm1, fmaxf(s10, s11));
            }
        }
        __syncthreads();   // Dbf/rs reuse next tile
    }

    // Reduce lm over t (4 lanes), write per-warp partials
    lm0 = fmaxf(lm0, __shfl_xor_sync(0xffffffffu, lm0, 1));
    lm0 = fmaxf(lm0, __shfl_xor_sync(0xffffffffu, lm0, 2));
    lm1 = fmaxf(lm1, __shfl_xor_sync(0xffffffffu, lm1, 1));
    lm1 = fmaxf(lm1, __shfl_xor_sync(0xffffffffu, lm1, 2));
    if (t == 0) {
        int wc = warp >> 1;
        qpart[(mq + g) * 8 + wc]     = lm0;
        qpart[(mq + g + 8) * 8 + wc] = lm1;
    }
    __syncthreads();

    if (tid < 32) {
        float v = NEGV;
#pragma unroll
        for (int j = 0; j < 8; j++) v = fmaxf(v, qpart[tid * 8 + j]);
#pragma unroll
        for (int o = 16; o >= 1; o >>= 1) v += __shfl_xor_sync(0xffffffffu, v, o, 32);
        if (tid == 0) out[b] = v;
    }
}

// ---------------------------------------------------------------------------
extern "C" void kernel_launch(void* const* d_in, const int* in_sizes, int n_in,
                              void* d_out, int out_size)
{
    const float* Qe   = (const float*)d_in[0];  // [128,32,768]
    const float* De   = (const float*)d_in[1];  // [128,1024,768]
    const int*   ids  = (const int*)  d_in[2];  // [128,1024]
    const int*   attn = (const int*)  d_in[3];  // [128,1024]
    const float* W    = (const float*)d_in[4];  // [128,768]
    float*       out  = (float*)d_out;          // [128]

    wconv_kernel<<<(DIMD * HH) / (256 * 4), 256>>>(W);
    compact_kernel<<<BB, 256>>>(attn);
    q_proj_kernel<<<BB, 256>>>(Qe, W);

    cudaFuncSetAttribute(score_kernel, cudaFuncAttributeMaxDynamicSharedMemorySize,
                         SM_TOTAL);
    score_kernel<<<BB, 512, SM_TOTAL>>>(De, ids, out);
}

// round 15
// speedup vs baseline: 3.3529x; 1.8218x over previous
#include <cuda_runtime.h>
#include <cuda_bf16.h>
#include <math.h>
#include <stdint.h>

// Problem constants
#define BB   128
#define QL   32
#define DL   1024
#define HH   768
#define DIMD 128
#define NEGV (-100000.0f)

// Scratch
__device__ __nv_bfloat16 g_Wbf[DIMD * HH];   // bf16 copy of W

// ---------------------------------------------------------------------------
// Helpers (base-ISA sm_80+)
// ---------------------------------------------------------------------------
__device__ __forceinline__ unsigned smem_u32(const void* p) {
    return (unsigned)__cvta_generic_to_shared(p);
}
__device__ __forceinline__ void cp_async16(unsigned dst, const void* src) {
    asm volatile("cp.async.cg.shared.global [%0], [%1], 16;\n" :: "r"(dst), "l"(src));
}
__device__ __forceinline__ void cp_commit() {
    asm volatile("cp.async.commit_group;\n" ::: "memory");
}
__device__ __forceinline__ void cp_wait2() {
    asm volatile("cp.async.wait_group 2;\n" ::: "memory");
}
__device__ __forceinline__ uint32_t f2bf2(float lo, float hi) {
    uint32_t r;
    asm("cvt.rn.bf16x2.f32 %0, %1, %2;" : "=r"(r) : "f"(hi), "f"(lo));
    return r;
}
__device__ __forceinline__ void ldsm_x4(uint32_t* r, uint32_t addr) {
    asm volatile("ldmatrix.sync.aligned.m8n8.x4.shared.b16 {%0,%1,%2,%3}, [%4];"
                 : "=r"(r[0]), "=r"(r[1]), "=r"(r[2]), "=r"(r[3]) : "r"(addr));
}
__device__ __forceinline__ void sts128(uint32_t addr, uint32_t r0, uint32_t r1,
                                       uint32_t r2, uint32_t r3) {
    asm volatile("st.shared.v4.b32 [%0], {%1,%2,%3,%4};"
                 :: "r"(addr), "r"(r0), "r"(r1), "r"(r2), "r"(r3) : "memory");
}
__device__ __forceinline__ void sts32(uint32_t addr, uint32_t r0) {
    asm volatile("st.shared.b32 [%0], %1;" :: "r"(addr), "r"(r0) : "memory");
}
__device__ __forceinline__ void mma_bf16(float* c, const uint32_t* a, const uint32_t* b) {
    asm volatile(
        "mma.sync.aligned.m16n8k16.row.col.f32.bf16.bf16.f32 "
        "{%0,%1,%2,%3}, {%4,%5,%6,%7}, {%8,%9}, {%0,%1,%2,%3};"
        : "+f"(c[0]), "+f"(c[1]), "+f"(c[2]), "+f"(c[3])
        : "r"(a[0]), "r"(a[1]), "r"(a[2]), "r"(a[3]), "r"(b[0]), "r"(b[1]));
}

// ---------------------------------------------------------------------------
// Kernel 0: W fp32 -> bf16
// ---------------------------------------------------------------------------
__global__ void wconv_kernel(const float* __restrict__ W)
{
    int i = blockIdx.x * 256 + threadIdx.x;
    float4 v = *(const float4*)(W + (size_t)i * 4);
    *(uint2*)((char*)g_Wbf + (size_t)i * 8) = make_uint2(f2bf2(v.x, v.y), f2bf2(v.z, v.w));
}

// ---------------------------------------------------------------------------
// Fused kernel: compaction + Q projection (rides tile 0) + D projection +
// mask + normalize + MMA scoring. 128 CTAs (one batch), 512 threads.
//
// Virtual row v = ti*128 + row - 32:
//   v < 0          -> Q row (tile 0, rows 0..31): epilogue -> Qbf + qsq
//   0 <= v < nk    -> compacted doc idx_s[v]
//   v >= nk        -> padding (doc 0, masked in score)
//
// SMEM bytes:
//   Qbf   0       8704    (32 x 128 bf16, stride 272)
//   Dbf   8704    34816   (128 x 128 bf16, stride 272)
//   A0    43520   18432   (128 x 64 bf16, stride 144)
//   A1    61952   18432
//   W0    80384   18432
//   W1    98816   18432
//   W2    117248  18432
//   W3    135680  18432
//   rs    154112  2048
//   dsq   156160  512
//   qsq   156672  128
//   qpart 156800  1024
//   idx   157824  4096    (compacted indices)
//   cnt   161920  128
//   total 162048
// ---------------------------------------------------------------------------
#define SM_QBF   0
#define SM_DBF   8704
#define SM_A0    43520
#define SM_A1    61952
#define SM_W0    80384
#define SM_W1    98816
#define SM_W2    117248
#define SM_W3    135680
#define SM_RS    154112
#define SM_DSQ   156160
#define SM_QSQ   156672
#define SM_QPART 156800
#define SM_IDX   157824
#define SM_CNT   161920
#define SM_TOTAL 162048

#define RSTR    144          // A/W row stride (64 bf16 + pad)
#define QSTR    272          // Qbf/Dbf row stride (128 bf16 + pad)
#define KC      64
#define NCHUNK  (HH / KC)    // 12

__global__ __launch_bounds__(512, 1)
void score_kernel(const float* __restrict__ Demb,
                  const float* __restrict__ Qe,
                  const int*   __restrict__ ids,
                  const int*   __restrict__ attn,
                  float*       __restrict__ out)
{
    extern __shared__ char smc[];
    float* rs    = (float*)(smc + SM_RS);
    float* dsq   = (float*)(smc + SM_DSQ);
    float* qsq   = (float*)(smc + SM_QSQ);
    float* qpart = (float*)(smc + SM_QPART);
    int*   idx_s = (int*)  (smc + SM_IDX);
    int*   cnt_s = (int*)  (smc + SM_CNT);

    const uint32_t base = smem_u32(smc);

    const int b    = blockIdx.x;
    const int tid  = threadIdx.x;
    const int lane = tid & 31;
    const int warp = tid >> 5;
    const int warpM = warp >> 2;       // 0..3 -> rows warpM*32..+31
    const int warpN = warp & 3;        // 0..3 -> cols warpN*32..+31
    const int g    = lane >> 2;        // 0..7
    const int t    = lane & 3;         // 0..3

    // A staging coords
    const int r0 = tid >> 3;           // 0..63
    const int c8 = tid & 7;

    // Main-GEMM ldmatrix offsets
    const uint32_t aoff = (uint32_t)(warpM * 32 + (lane & 15)) * RSTR
                        + ((lane >> 4) & 1) * 16;
    const uint32_t boff = (uint32_t)(warpN * 32 + ((lane >> 4) & 1) * 8 + (lane & 7)) * RSTR
                        + ((lane >> 3) & 1) * 16;
    const uint32_t Au[2]   = {base + SM_A0 + aoff, base + SM_A1 + aoff};
    const uint32_t Adst[2] = {base + SM_A0, base + SM_A1};
    const uint32_t Wu[4]   = {base + SM_W0 + boff, base + SM_W1 + boff,
                              base + SM_W2 + boff, base + SM_W3 + boff};
    const uint32_t Wdst[4] = {base + SM_W0, base + SM_W1, base + SM_W2, base + SM_W3};

    // Score-GEMM offsets: each warp does m16 x two n8 tiles (n0 and n0+64)
    const int mq = (warp & 1) * 16;
    const int n0 = (warp >> 1) * 8;
    const uint32_t qa = base + SM_QBF + (uint32_t)(mq + (lane & 15)) * QSTR
                      + ((lane >> 4) & 1) * 16;
    const uint32_t da0 = base + SM_DBF + (uint32_t)(n0 + (lane & 7)) * QSTR
                       + ((lane >> 3) & 3) * 16;
    const uint32_t da1 = da0 + 64 * QSTR;

    // ---- In-kernel compaction: ballot + one shared atomic per warp-chunk ----
    if (tid == 0) *cnt_s = 0;
    __syncthreads();
    for (int c = warp; c < 32; c += 16) {          // 32 chunks of 32 docs
        int j = c * 32 + lane;
        int v = attn[b * DL + j];
        unsigned m = __ballot_sync(0xffffffffu, v != 0);
        int bofs = 0;
        if (lane == 0) bofs = atomicAdd(cnt_s, __popc(m));
        bofs = __shfl_sync(0xffffffffu, bofs, 0);
        if (v != 0)
            idx_s[bofs + __popc(m & ((1u << lane) - 1u))] = j;
    }
    __syncthreads();
    const int nk = *cnt_s;
    const int ntiles = (nk + 32 + 127) >> 7;       // +32 virtual Q rows

    const float* Qrow  = Qe   + (size_t)b * QL * HH;
    const float* Drow  = Demb + (size_t)b * DL * HH;

    float lm0 = NEGV, lm1 = NEGV;      // running max for query rows mq+g, mq+g+8

    for (int ti = 0; ti < ntiles; ti++) {
        const int vbase = ti * 128 - 32;

        // Gather source rows for this thread's two staged rows
        const int v0 = vbase + r0;
        const int v1 = vbase + r0 + 64;             // always >= 32 -> doc
        const float* a0p = (v0 < 0)
            ? Qrow + (size_t)r0 * HH + c8 * 8
            : Drow + (size_t)((v0 < nk) ? idx_s[v0] : 0) * HH + c8 * 8;
        const float* a1p =
              Drow + (size_t)((v1 < nk) ? idx_s[v1] : 0) * HH + c8 * 8;

        float acc[2][4][4];
#pragma unroll
        for (int m = 0; m < 2; m++)
#pragma unroll
            for (int n = 0; n < 4; n++)
#pragma unroll
                for (int r = 0; r < 4; r++) acc[m][n][r] = 0.0f;

        // Prologue: LDG A chunks 0,1 -> regs; cp.async W chunks 0,1,2
        float4 ra[2][4];
#pragma unroll
        for (int c = 0; c < 2; c++) {
            ra[c][0] = *(const float4*)(a0p + c * KC);
            ra[c][1] = *(const float4*)(a0p + c * KC + 4);
            ra[c][2] = *(const float4*)(a1p + c * KC);
            ra[c][3] = *(const float4*)(a1p + c * KC + 4);
        }
#pragma unroll
        for (int c = 0; c < 3; c++) {
#pragma unroll
            for (int l = 0; l < 2; l++) {
                int lin = tid + l * 512;
                int wr  = lin >> 3;
                int c16 = lin & 7;
                cp_async16(Wdst[c] + wr * RSTR + c16 * 16,
                           (const char*)g_Wbf + (size_t)wr * (HH * 2)
                               + c * (KC * 2) + c16 * 16);
            }
            cp_commit();
        }

        for (int s = 0; s < NCHUNK; s++) {
            // 1. STS chunk s A
            const uint32_t ab = Adst[s & 1] + (uint32_t)r0 * RSTR + c8 * 16;
            sts128(ab,
                   f2bf2(ra[s & 1][0].x, ra[s & 1][0].y), f2bf2(ra[s & 1][0].z, ra[s & 1][0].w),
                   f2bf2(ra[s & 1][1].x, ra[s & 1][1].y), f2bf2(ra[s & 1][1].z, ra[s & 1][1].w));
            sts128(ab + 64 * RSTR,
                   f2bf2(ra[s & 1][2].x, ra[s & 1][2].y), f2bf2(ra[s & 1][2].z, ra[s & 1][2].w),
                   f2bf2(ra[s & 1][3].x, ra[s & 1][3].y), f2bf2(ra[s & 1][3].z, ra[s & 1][3].w));

            // 2. LDG chunk s+2 (distance 2)
            if (s + 2 < NCHUNK) {
                ra[s & 1][0] = *(const float4*)(a0p + (s + 2) * KC);
                ra[s & 1][1] = *(const float4*)(a0p + (s + 2) * KC + 4);
                ra[s & 1][2] = *(const float4*)(a1p + (s + 2) * KC);
                ra[s & 1][3] = *(const float4*)(a1p + (s + 2) * KC + 4);
            }

            // 3. Wait W chunk s, then barrier
            cp_wait2();
            __syncthreads();

            // 4. cp.async W chunk s+3 (safe after barrier: MMA s-1 done)
            if (s + 3 < NCHUNK) {
                uint32_t wdst = Wdst[(s + 3) & 3];
#pragma unroll
                for (int l = 0; l < 2; l++) {
                    int lin = tid + l * 512;
                    int wr  = lin >> 3;
                    int c16 = lin & 7;
                    cp_async16(wdst + wr * RSTR + c16 * 16,
                               (const char*)g_Wbf + (size_t)wr * (HH * 2)
                                   + (s + 3) * (KC * 2) + c16 * 16);
                }
            }
            cp_commit();   // unconditional: uniform group indexing

            // 5. MMA chunk s
            const uint32_t au = Au[s & 1];
            const uint32_t wb = Wu[s & 3];
#pragma unroll
            for (int kb = 0; kb < 4; kb++) {
                uint32_t a0[4], a1[4], b0[4], b1[4];
                ldsm_x4(a0, au + kb * 32);
                ldsm_x4(a1, au + 16 * RSTR + kb * 32);
                ldsm_x4(b0, wb + kb * 32);
                ldsm_x4(b1, wb + 16 * RSTR + kb * 32);
                mma_bf16(acc[0][0], a0, b0);
                mma_bf16(acc[0][1], a0, b0 + 2);
                mma_bf16(acc[0][2], a0, b1);
                mma_bf16(acc[0][3], a0, b1 + 2);
                mma_bf16(acc[1][0], a1, b0);
                mma_bf16(acc[1][1], a1, b0 + 2);
                mma_bf16(acc[1][2], a1, b1);
                mma_bf16(acc[1][3], a1, b1 + 2);
            }
        }

        // ---- Epilogue: mask (docs only) + row-norm partials ----
#pragma unroll
        for (int m = 0; m < 2; m++) {
#pragma unroll
            for (int h = 0; h < 2; h++) {
                int row = warpM * 32 + m * 16 + h * 8 + g;
                int v   = vbase + row;
                bool z  = false;
                if (v >= 0 && v < nk) z = (ids[b * DL + idx_s[v]] == 0);
                float s = 0.0f;
#pragma unroll
                for (int n = 0; n < 4; n++) {
                    if (z) { acc[m][n][h * 2] = 0.0f; acc[m][n][h * 2 + 1] = 0.0f; }
                    float x = acc[m][n][h * 2];
                    float y = acc[m][n][h * 2 + 1];
                    s += x * x + y * y;
                }
                s += __shfl_xor_sync(0xffffffffu, s, 1, 4);
                s += __shfl_xor_sync(0xffffffffu, s, 2, 4);
                if (t == 0) rs[warpN * 128 + row] = s;
            }
        }
        __syncthreads();

        // ---- Normalize -> bf16 Qbf (v<0) or Dbf (v>=0); qsq/dsq ----
#pragma unroll
        for (int m = 0; m < 2; m++) {
#pragma unroll
            for (int h = 0; h < 2; h++) {
                int row   = warpM * 32 + m * 16 + h * 8 + g;
                int v     = vbase + row;
                float st  = rs[row] + rs[128 + row] + rs[256 + row] + rs[384 + row];
                float inv = 1.0f / fmaxf(sqrtf(st), 1e-12f);
                const bool isQ = (v < 0);   // warp-uniform (row block < 32)
                uint32_t dstb = isQ ? (base + SM_QBF) : (base + SM_DBF);
#pragma unroll
                for (int n = 0; n < 4; n++) {
                    int col = warpN * 32 + n * 8 + t * 2;
                    uint32_t pk = f2bf2(acc[m][n][h * 2] * inv, acc[m][n][h * 2 + 1] * inv);
                    sts32(dstb + (uint32_t)row * QSTR + col * 2, pk);
                }
                if (warpN == 0 && t == 0) {
                    if (isQ) qsq[row] = st * inv * inv;
                    else     dsq[row] = st * inv * inv;
                }
            }
        }
        __syncthreads();

        // ---- Score GEMM: S = Q . D^T; validity = 0 <= vcol < nk ----
        {
            const float q0 = qsq[mq + g], q1 = qsq[mq + g + 8];
#pragma unroll
            for (int half = 0; half < 2; half++) {
                const uint32_t da = half ? da1 : da0;
                float sacc[4] = {0.0f, 0.0f, 0.0f, 0.0f};
#pragma unroll
                for (int kb = 0; kb < 8; kb += 2) {
                    uint32_t aA[4], aB[4], bb[4];
                    ldsm_x4(aA, qa + kb * 32);
                    ldsm_x4(aB, qa + (kb + 1) * 32);
                    ldsm_x4(bb, da + kb * 32);
                    mma_bf16(sacc, aA, bb);
                    mma_bf16(sacc, aB, bb + 2);
                }
                const int col0 = n0 + half * 64 + t * 2;
                const int col1 = col0 + 1;
                const int vc0  = vbase + col0;
                const int vc1  = vbase + col1;
                const bool k0  = (vc0 >= 0) && (vc0 < nk);
                const bool k1  = (vc1 >= 0) && (vc1 < nk);
                const float d0 = dsq[col0], d1 = dsq[col1];
                float s00 = k0 ? (2.0f * sacc[0] - q0 - d0) : NEGV;
                float s01 = k1 ? (2.0f * sacc[1] - q0 - d1) : NEGV;
                float s10 = k0 ? (2.0f * sacc[2] - q1 - d0) : NEGV;
                float s11 = k1 ? (2.0f * sacc[3] - q1 - d1) : NEGV;
                lm0 = fmaxf(lm0, fmaxf(s00, s01));
                lm1 = fmaxf(lm1, fmaxf(s10, s11));
            }
        }
        __syncthreads();   // Dbf/rs reuse next tile
    }

    // Reduce lm over t (4 lanes), write per-warp partials
    lm0 = fmaxf(lm0, __shfl_xor_sync(0xffffffffu, lm0, 1));
    lm0 = fmaxf(lm0, __shfl_xor_sync(0xffffffffu, lm0, 2));
    lm1 = fmaxf(lm1, __shfl_xor_sync(0xffffffffu, lm1, 1));
    lm1 = fmaxf(lm1, __shfl_xor_sync(0xffffffffu, lm1, 2));
    if (t == 0) {
        int wc = warp >> 1;
        qpart[(mq + g) * 8 + wc]     = lm0;
        qpart[(mq + g + 8) * 8 + wc] = lm1;
    }
    __syncthreads();

    if (tid < 32) {
        float v = NEGV;
#pragma unroll
        for (int j = 0; j < 8; j++) v = fmaxf(v, qpart[tid * 8 + j]);
#pragma unroll
        for (int o = 16; o >= 1; o >>= 1) v += __shfl_xor_sync(0xffffffffu, v, o, 32);
        if (tid == 0) out[b] = v;
    }
}

// ---------------------------------------------------------------------------
extern "C" void kernel_launch(void* const* d_in, const int* in_sizes, int n_in,
                              void* d_out, int out_size)
{
    const float* Qe   = (const float*)d_in[0];  // [128,32,768]
    const float* De   = (const float*)d_in[1];  // [128,1024,768]
    const int*   ids  = (const int*)  d_in[2];  // [128,1024]
    const int*   attn = (const int*)  d_in[3];  // [128,1024]
    const float* W    = (const float*)d_in[4];  // [128,768]
    float*       out  = (float*)d_out;          // [128]

    wconv_kernel<<<(DIMD * HH) / (256 * 4), 256>>>(W);

    cudaFuncSetAttribute(score_kernel, cudaFuncAttributeMaxDynamicSharedMemorySize,
                         SM_TOTAL);
    score_kernel<<<BB, 512, SM_TOTAL>>>(De, Qe, ids, attn, out);
}